// round 1
// baseline (speedup 1.0000x reference)
#include <cuda_runtime.h>
#include <cuda_bf16.h>
#include <math.h>

// ---------------- problem constants ----------------
#define BSZ   2
#define LSEQ  4096
#define TTOT  8192          // BSZ*LSEQ
#define HIDD  768
#define IF    1536          // I
#define NST   128           // N
#define HH    24            // H
#define PP    64            // P
#define CSZ   256           // chunk size
#define CN    16            // LSEQ/CSZ
#define KC    4             // conv kernel
#define NPROJ 3352          // 2*(I+N)+H
#define XBCW  1792          // I+2N

// ---------------- scratch (static device globals; no allocs) ----------------
__device__ float g_zx[TTOT * NPROJ];               // in_proj output (z | xBC | dt)
__device__ float g_xc[TTOT * XBCW];                // conv+silu output
__device__ float g_dt[TTOT * HH];                  // softplus(dt+bias)
__device__ float g_ac[BSZ * HH * CN * CSZ];        // per-chunk inclusive cumsum of A*dt
__device__ float g_ls[BSZ * CN * HH * PP * NST];   // local chunk states  [b][c][h][p][n]
__device__ float g_ps[BSZ * CN * HH * PP * NST];   // prefix states entering chunk
__device__ float g_y [TTOT * IF];                  // y before / after gated norm (in-place)

// ---------------- generic fp32 SGEMM: C = A(MxK) * B(KxN), row-major ----------------
// BM=BN=128, BK=8, 256 threads, 8x8 per thread. M%128==0, K%8==0 required.
__global__ __launch_bounds__(256) void sgemm_kernel(const float* __restrict__ A,
                                                    const float* __restrict__ B,
                                                    float* __restrict__ C,
                                                    int M, int N, int K) {
    __shared__ float As[8][128];
    __shared__ float Bs[8][128];
    const int tid = threadIdx.x;
    const int rowBase = blockIdx.y * 128;
    const int colBase = blockIdx.x * 128;

    const int aRow  = tid >> 1;          // 0..127
    const int aCol4 = (tid & 1) * 4;     // 0 or 4
    const int bRow  = tid >> 5;          // 0..7
    const int bCol4 = (tid & 31) * 4;    // 0..124
    const int tr = tid >> 4, tc = tid & 15;

    float acc[8][8];
#pragma unroll
    for (int i = 0; i < 8; i++)
#pragma unroll
        for (int j = 0; j < 8; j++) acc[i][j] = 0.f;

    for (int k0 = 0; k0 < K; k0 += 8) {
        // A tile (always in-bounds): 128 rows x 8 k
        float4 av = *reinterpret_cast<const float4*>(&A[(size_t)(rowBase + aRow) * K + k0 + aCol4]);
        As[aCol4 + 0][aRow] = av.x;
        As[aCol4 + 1][aRow] = av.y;
        As[aCol4 + 2][aRow] = av.z;
        As[aCol4 + 3][aRow] = av.w;
        // B tile: 8 rows x 128 cols, guard cols
        int gcol = colBase + bCol4;
        if (gcol + 3 < N) {
            float4 bv = *reinterpret_cast<const float4*>(&B[(size_t)(k0 + bRow) * N + gcol]);
            Bs[bRow][bCol4 + 0] = bv.x;
            Bs[bRow][bCol4 + 1] = bv.y;
            Bs[bRow][bCol4 + 2] = bv.z;
            Bs[bRow][bCol4 + 3] = bv.w;
        } else {
#pragma unroll
            for (int j = 0; j < 4; j++)
                Bs[bRow][bCol4 + j] = (gcol + j < N) ? B[(size_t)(k0 + bRow) * N + gcol + j] : 0.f;
        }
        __syncthreads();
#pragma unroll
        for (int kk = 0; kk < 8; kk++) {
            float ra[8], rb[8];
            float4 a0 = *reinterpret_cast<const float4*>(&As[kk][tr * 8]);
            float4 a1 = *reinterpret_cast<const float4*>(&As[kk][tr * 8 + 4]);
            ra[0]=a0.x; ra[1]=a0.y; ra[2]=a0.z; ra[3]=a0.w; ra[4]=a1.x; ra[5]=a1.y; ra[6]=a1.z; ra[7]=a1.w;
            float4 b0 = *reinterpret_cast<const float4*>(&Bs[kk][tc * 8]);
            float4 b1 = *reinterpret_cast<const float4*>(&Bs[kk][tc * 8 + 4]);
            rb[0]=b0.x; rb[1]=b0.y; rb[2]=b0.z; rb[3]=b0.w; rb[4]=b1.x; rb[5]=b1.y; rb[6]=b1.z; rb[7]=b1.w;
#pragma unroll
            for (int i = 0; i < 8; i++)
#pragma unroll
                for (int j = 0; j < 8; j++) acc[i][j] = fmaf(ra[i], rb[j], acc[i][j]);
        }
        __syncthreads();
    }
#pragma unroll
    for (int i = 0; i < 8; i++) {
        int row = rowBase + tr * 8 + i;
#pragma unroll
        for (int j = 0; j < 8; j++) {
            int col = colBase + tc * 8 + j;
            if (col < N) C[(size_t)row * N + col] = acc[i][j];
        }
    }
}

// ---------------- conv1d (causal depthwise, K=4) + bias + silu ----------------
__global__ __launch_bounds__(256) void conv_kernel(const float* __restrict__ cw,
                                                   const float* __restrict__ cb) {
    int ch = blockIdx.x * 256 + threadIdx.x;   // < 1792
    int t  = blockIdx.y;
    int b  = t / LSEQ, l = t % LSEQ;
    float acc = cb[ch];
#pragma unroll
    for (int k = 0; k < KC; k++) {
        int lp = l - (KC - 1) + k;
        if (lp >= 0)
            acc = fmaf(g_zx[(size_t)(b * LSEQ + lp) * NPROJ + IF + ch], cw[k * XBCW + ch], acc);
    }
    acc = acc / (1.f + expf(-acc));   // silu
    g_xc[(size_t)t * XBCW + ch] = acc;
}

// ---------------- dt: softplus(dt_raw + bias), clip>=0 ----------------
__global__ __launch_bounds__(256) void dt_kernel(const float* __restrict__ dtb) {
    int idx = blockIdx.x * 256 + threadIdx.x;
    if (idx >= TTOT * HH) return;
    int t = idx / HH, h = idx % HH;
    float x = g_zx[(size_t)t * NPROJ + (NPROJ - HH) + h] + dtb[h];
    float sp = (x > 0.f) ? (x + log1pf(expf(-x))) : log1pf(expf(x));
    g_dt[idx] = fmaxf(sp, 0.f);
}

// ---------------- per-chunk inclusive cumsum of A*dt ----------------
__global__ __launch_bounds__(256) void acum_kernel(const float* __restrict__ alog) {
    int bx = blockIdx.x;                 // b*H*C blocks
    int c  = bx % CN;
    int h  = (bx / CN) % HH;
    int b  = bx / (CN * HH);
    int s  = threadIdx.x;
    int t  = b * LSEQ + c * CSZ + s;
    float A = -expf(alog[h]);
    __shared__ float a[CSZ];
    a[s] = A * g_dt[(size_t)t * HH + h];
    __syncthreads();
    for (int off = 1; off < CSZ; off <<= 1) {
        float add = (s >= off) ? a[s - off] : 0.f;
        __syncthreads();
        a[s] += add;
        __syncthreads();
    }
    g_ac[(size_t)((b * HH + h) * CN + c) * CSZ + s] = a[s];
}

// ---------------- local chunk state: S[p][n] = sum_l B[l,n]*exp(Asum-Acum[l])*x[l,p]*dt[l] -----
__global__ __launch_bounds__(256) void chunkstate_kernel() {
    extern __shared__ float sm[];
    float* Bs = sm;               // 64 x 130
    float* Xs = sm + 64 * 130;    // 64 x 66
    int bx = blockIdx.x;
    int h = bx % HH;
    int c = (bx / HH) % CN;
    int b = bx / (HH * CN);
    int tid = threadIdx.x;
    int ty = tid >> 4, tx = tid & 15;
    int acbase = ((b * HH + h) * CN + c) * CSZ;
    float Asum = g_ac[acbase + CSZ - 1];
    float acc[4][8];
#pragma unroll
    for (int i = 0; i < 4; i++)
#pragma unroll
        for (int j = 0; j < 8; j++) acc[i][j] = 0.f;

    for (int lt = 0; lt < 4; lt++) {
        for (int i = tid; i < 64 * 128; i += 256) {
            int s = i >> 7, n = i & 127;
            int ts = b * LSEQ + c * CSZ + lt * 64 + s;
            float dec = expf(Asum - g_ac[acbase + lt * 64 + s]);
            Bs[s * 130 + n] = g_xc[(size_t)ts * XBCW + IF + n] * dec;
        }
        for (int i = tid; i < 64 * 64; i += 256) {
            int s = i >> 6, p = i & 63;
            int ts = b * LSEQ + c * CSZ + lt * 64 + s;
            Xs[s * 66 + p] = g_xc[(size_t)ts * XBCW + h * PP + p] * g_dt[(size_t)ts * HH + h];
        }
        __syncthreads();
        for (int s = 0; s < 64; s++) {
            float xv[4], bv[8];
#pragma unroll
            for (int i = 0; i < 4; i++) xv[i] = Xs[s * 66 + ty * 4 + i];
#pragma unroll
            for (int j = 0; j < 8; j++) bv[j] = Bs[s * 130 + tx * 8 + j];
#pragma unroll
            for (int i = 0; i < 4; i++)
#pragma unroll
                for (int j = 0; j < 8; j++) acc[i][j] = fmaf(xv[i], bv[j], acc[i][j]);
        }
        __syncthreads();
    }
    size_t base = ((size_t)((b * CN + c) * HH + h)) * PP * NST;
#pragma unroll
    for (int i = 0; i < 4; i++) {
        int p = ty * 4 + i;
#pragma unroll
        for (int j = 0; j < 8; j++) {
            int n = tx * 8 + j;
            g_ls[base + (size_t)p * NST + n] = acc[i][j];
        }
    }
}

// ---------------- inter-chunk recurrence over 16 chunks ----------------
__global__ __launch_bounds__(256) void recur_kernel() {
    int bh = blockIdx.x;   // 48
    int b = bh / HH, h = bh % HH;
    int tid = threadIdx.x;
    float st[32];
#pragma unroll
    for (int e = 0; e < 32; e++) st[e] = 0.f;
    for (int c = 0; c < CN; c++) {
        float es = expf(g_ac[(size_t)((b * HH + h) * CN + c) * CSZ + CSZ - 1]);
        size_t base = ((size_t)((b * CN + c) * HH + h)) * PP * NST;
#pragma unroll
        for (int e = 0; e < 32; e++) {
            int idx = tid + e * 256;
            g_ps[base + idx] = st[e];
            st[e] = fmaf(st[e], es, g_ls[base + idx]);
        }
    }
}

// ---------------- Y = (masked C B^T L) @ Xd  +  exp(Acum) * C @ S^T  +  D*x ----------------
__global__ __launch_bounds__(256) void ydiag_kernel(const float* __restrict__ Darr) {
    extern __shared__ float sm[];
    float* Cs = sm;                 // 64 x 130
    float* Bs = Cs + 64 * 130;      // 64 x 130  (B tiles, later S)
    float* Xs = Bs + 64 * 130;      // 64 x 66
    float* Gs = Xs + 64 * 66;       // 64 x 66
    float* aL = Gs + 64 * 66;       // 64
    float* aS = aL + 64;            // 64
    float* eA = aS + 64;            // 64

    int lt  = blockIdx.x;           // 0..3
    int bch = blockIdx.y;           // 768
    int h = bch % HH;
    int c = (bch / HH) % CN;
    int b = bch / (HH * CN);
    int tid = threadIdx.x;
    int ty = tid >> 4, tx = tid & 15;
    int acbase = ((b * HH + h) * CN + c) * CSZ;

    // C tile + aL
    for (int i = tid; i < 64 * 128; i += 256) {
        int l = i >> 7, n = i & 127;
        int t = b * LSEQ + c * CSZ + lt * 64 + l;
        Cs[l * 130 + n] = g_xc[(size_t)t * XBCW + IF + NST + n];
    }
    if (tid < 64) aL[tid] = g_ac[acbase + lt * 64 + tid];

    float acc[4][4];
#pragma unroll
    for (int i = 0; i < 4; i++)
#pragma unroll
        for (int j = 0; j < 4; j++) acc[i][j] = 0.f;

    for (int st = 0; st <= lt; st++) {
        __syncthreads();
        for (int i = tid; i < 64 * 128; i += 256) {
            int s = i >> 7, n = i & 127;
            int ts = b * LSEQ + c * CSZ + st * 64 + s;
            Bs[s * 130 + n] = g_xc[(size_t)ts * XBCW + IF + n];
        }
        for (int i = tid; i < 64 * 64; i += 256) {
            int s = i >> 6, p = i & 63;
            int ts = b * LSEQ + c * CSZ + st * 64 + s;
            Xs[s * 66 + p] = g_xc[(size_t)ts * XBCW + h * PP + p] * g_dt[(size_t)ts * HH + h];
        }
        if (tid < 64) aS[tid] = g_ac[acbase + st * 64 + tid];
        __syncthreads();
        // G = (C · B) * mask*exp(aL-aS)
        float g[4][4];
#pragma unroll
        for (int i = 0; i < 4; i++)
#pragma unroll
            for (int j = 0; j < 4; j++) g[i][j] = 0.f;
        for (int n = 0; n < 128; n++) {
            float cv[4], bv[4];
#pragma unroll
            for (int i = 0; i < 4; i++) cv[i] = Cs[(ty * 4 + i) * 130 + n];
#pragma unroll
            for (int j = 0; j < 4; j++) bv[j] = Bs[(tx * 4 + j) * 130 + n];
#pragma unroll
            for (int i = 0; i < 4; i++)
#pragma unroll
                for (int j = 0; j < 4; j++) g[i][j] = fmaf(cv[i], bv[j], g[i][j]);
        }
#pragma unroll
        for (int i = 0; i < 4; i++) {
            int gl = lt * 64 + ty * 4 + i;
#pragma unroll
            for (int j = 0; j < 4; j++) {
                int gs = st * 64 + tx * 4 + j;
                float f = (gs <= gl) ? expf(aL[ty * 4 + i] - aS[tx * 4 + j]) : 0.f;
                Gs[(ty * 4 + i) * 66 + (tx * 4 + j)] = g[i][j] * f;
            }
        }
        __syncthreads();
        // Y += G @ Xd
        for (int s = 0; s < 64; s++) {
            float gv[4], xv[4];
#pragma unroll
            for (int i = 0; i < 4; i++) gv[i] = Gs[(ty * 4 + i) * 66 + s];
#pragma unroll
            for (int j = 0; j < 4; j++) xv[j] = Xs[s * 66 + tx * 4 + j];
#pragma unroll
            for (int i = 0; i < 4; i++)
#pragma unroll
                for (int j = 0; j < 4; j++) acc[i][j] = fmaf(gv[i], xv[j], acc[i][j]);
        }
    }
    __syncthreads();
    // Y_off: load prefix state S[p][n] into Bs, acc += exp(aL)*C@S^T
    {
        size_t base = ((size_t)((b * CN + c) * HH + h)) * PP * NST;
        for (int i = tid; i < 64 * 128; i += 256) {
            int p = i >> 7, n = i & 127;
            Bs[p * 130 + n] = g_ps[base + (size_t)p * NST + n];
        }
        if (tid < 64) eA[tid] = expf(aL[tid]);
        __syncthreads();
        float off[4][4];
#pragma unroll
        for (int i = 0; i < 4; i++)
#pragma unroll
            for (int j = 0; j < 4; j++) off[i][j] = 0.f;
        for (int n = 0; n < 128; n++) {
            float cv[4], sv[4];
#pragma unroll
            for (int i = 0; i < 4; i++) cv[i] = Cs[(ty * 4 + i) * 130 + n];
#pragma unroll
            for (int j = 0; j < 4; j++) sv[j] = Bs[(tx * 4 + j) * 130 + n];
#pragma unroll
            for (int i = 0; i < 4; i++)
#pragma unroll
                for (int j = 0; j < 4; j++) off[i][j] = fmaf(cv[i], sv[j], off[i][j]);
        }
#pragma unroll
        for (int i = 0; i < 4; i++)
#pragma unroll
            for (int j = 0; j < 4; j++) acc[i][j] += eA[ty * 4 + i] * off[i][j];
    }
    // store + D residual
    float Dh = Darr[h];
#pragma unroll
    for (int i = 0; i < 4; i++) {
        int t = b * LSEQ + c * CSZ + lt * 64 + ty * 4 + i;
#pragma unroll
        for (int j = 0; j < 4; j++) {
            int p = tx * 4 + j;
            float xraw = g_xc[(size_t)t * XBCW + h * PP + p];
            g_y[(size_t)t * IF + h * PP + p] = acc[i][j] + Dh * xraw;
        }
    }
}

// ---------------- gated RMSNorm (in-place on g_y) ----------------
__global__ __launch_bounds__(256) void gnorm_kernel(const float* __restrict__ nw) {
    int t = blockIdx.x;
    int tid = threadIdx.x;
    float vals[6];
    float ss = 0.f;
#pragma unroll
    for (int k = 0; k < 6; k++) {
        int i = tid + k * 256;
        float y = g_y[(size_t)t * IF + i];
        float z = g_zx[(size_t)t * NPROJ + i];
        float xf = y * (z / (1.f + expf(-z)));
        vals[k] = xf;
        ss += xf * xf;
    }
    __shared__ float red[256];
    __shared__ float s_scale;
    red[tid] = ss;
    __syncthreads();
    for (int o = 128; o > 0; o >>= 1) {
        if (tid < o) red[tid] += red[tid + o];
        __syncthreads();
    }
    if (tid == 0) s_scale = rsqrtf(red[0] / (float)IF + 1e-5f);
    __syncthreads();
    float sc = s_scale;
#pragma unroll
    for (int k = 0; k < 6; k++) {
        int i = tid + k * 256;
        g_y[(size_t)t * IF + i] = vals[k] * sc * nw[i];
    }
}

// ---------------- host launcher ----------------
extern "C" void kernel_launch(void* const* d_in, const int* in_sizes, int n_in,
                              void* d_out, int out_size) {
    const float* hs   = (const float*)d_in[0];
    const float* inw  = (const float*)d_in[1];
    const float* cw   = (const float*)d_in[2];
    const float* cb   = (const float*)d_in[3];
    const float* dtb  = (const float*)d_in[4];
    const float* alog = (const float*)d_in[5];
    const float* Dp   = (const float*)d_in[6];
    const float* nw   = (const float*)d_in[7];
    const float* ow   = (const float*)d_in[8];
    float* out = (float*)d_out;

    void *p_zx = nullptr, *p_y = nullptr;
    cudaGetSymbolAddress(&p_zx, g_zx);
    cudaGetSymbolAddress(&p_y, g_y);

    // opt-in smem sizes
    int smem_cs = (64 * 130 + 64 * 66) * 4;                       // 50176
    int smem_y  = (64 * 130 * 2 + 64 * 66 * 2 + 3 * 64) * 4;      // 101120
    cudaFuncSetAttribute(chunkstate_kernel, cudaFuncAttributeMaxDynamicSharedMemorySize, smem_cs);
    cudaFuncSetAttribute(ydiag_kernel, cudaFuncAttributeMaxDynamicSharedMemorySize, smem_y);

    // 1. in_proj GEMM: (8192 x 768) @ (768 x 3352)
    {
        dim3 grid((NPROJ + 127) / 128, TTOT / 128);
        sgemm_kernel<<<grid, 256>>>(hs, inw, (float*)p_zx, TTOT, NPROJ, HIDD);
    }
    // 2. conv + silu
    {
        dim3 grid(XBCW / 256, TTOT);
        conv_kernel<<<grid, 256>>>(cw, cb);
    }
    // 3. dt softplus
    dt_kernel<<<(TTOT * HH + 255) / 256, 256>>>(dtb);
    // 4. per-chunk cumsum of A*dt
    acum_kernel<<<BSZ * HH * CN, 256>>>(alog);
    // 5. local chunk states
    chunkstate_kernel<<<BSZ * CN * HH, 256, smem_cs>>>();
    // 6. inter-chunk recurrence
    recur_kernel<<<BSZ * HH, 256>>>();
    // 7. Y_diag + Y_off + D residual
    {
        dim3 grid(4, BSZ * CN * HH);
        ydiag_kernel<<<grid, 256, smem_y>>>(Dp);
    }
    // 8. gated RMSNorm
    gnorm_kernel<<<TTOT, 256>>>(nw);
    // 9. out_proj GEMM: (8192 x 1536) @ (1536 x 768) -> d_out
    {
        dim3 grid(HIDD / 128, TTOT / 128);
        sgemm_kernel<<<grid, 256>>>((const float*)p_y, ow, out, TTOT, HIDD, IF);
    }
}

// round 2
// speedup vs baseline: 1.4962x; 1.4962x over previous
#include <cuda_runtime.h>
#include <cuda_bf16.h>
#include <math.h>
#include <stdint.h>

// ---------------- problem constants ----------------
#define BSZ   2
#define LSEQ  4096
#define TTOT  8192          // BSZ*LSEQ
#define HIDD  768
#define IF    1536          // I
#define NST   128           // N
#define HH    24            // H
#define PP    64            // P
#define CSZ   256           // chunk size
#define CN    16            // LSEQ/CSZ
#define KC    4             // conv kernel
#define NPROJ 3352          // 2*(I+N)+H
#define XBCW  1792          // I+2N

// ---------------- scratch (static device globals; no allocs) ----------------
__device__ float g_zx[TTOT * NPROJ];               // in_proj output (z | xBC | dt)
__device__ float g_xc[TTOT * XBCW];                // conv+silu output
__device__ float g_dt[TTOT * HH];                  // softplus(dt+bias)
__device__ float g_ac[BSZ * HH * CN * CSZ];        // per-chunk inclusive cumsum of A*dt
__device__ float g_ls[BSZ * CN * HH * PP * NST];   // local chunk states  [b][c][h][p][n]
__device__ float g_ps[BSZ * CN * HH * PP * NST];   // prefix states entering chunk
__device__ float g_y [TTOT * IF];                  // y before / after gated norm (in-place)

// ================= TF32 tensor-core GEMM =================
// C = A(MxK) * B(KxN), row-major fp32 in/out, tf32 mma.sync.m16n8k8.
// BM=BN=128, BK=16, 256 threads = 8 warps (2x4), warp tile 64x32.
// M % 128 == 0, K % 16 == 0 required; N guarded.

__device__ __forceinline__ float f2tf32(float x) {
    uint32_t r;
    asm("cvt.rna.tf32.f32 %0, %1;" : "=r"(r) : "f"(x));
    return __uint_as_float(r);
}

#define AS_STRIDE 20     // 16 + 4 pad  -> conflict-free fragment loads
#define BS_STRIDE 136    // 128 + 8 pad -> conflict-free fragment loads

__global__ __launch_bounds__(256) void tf32gemm_kernel(const float* __restrict__ A,
                                                       const float* __restrict__ B,
                                                       float* __restrict__ C,
                                                       int M, int N, int K) {
    __shared__ float As[2][128 * AS_STRIDE];
    __shared__ float Bs[2][16 * BS_STRIDE];

    const int tid   = threadIdx.x;
    const int lane  = tid & 31;
    const int warpId = tid >> 5;
    const int gid   = lane >> 2;   // 0..7
    const int tig   = lane & 3;    // 0..3
    const int warpM = warpId & 1;  // 0..1
    const int warpN = warpId >> 1; // 0..3
    const int rowBase = blockIdx.y * 128;
    const int colBase = blockIdx.x * 128;

    float acc[4][4][4];
#pragma unroll
    for (int mt = 0; mt < 4; mt++)
#pragma unroll
        for (int nt = 0; nt < 4; nt++)
#pragma unroll
            for (int e = 0; e < 4; e++) acc[mt][nt][e] = 0.f;

    float4 ar[2], br[2];
    const int nk = K >> 4;

    // ---- loaders ----
    auto loadA = [&](int k0) {
#pragma unroll
        for (int i = 0; i < 2; i++) {
            int f = tid * 2 + i;
            int row = f >> 2, c4 = (f & 3) * 4;
            ar[i] = *reinterpret_cast<const float4*>(&A[(size_t)(rowBase + row) * K + k0 + c4]);
        }
    };
    auto storeA = [&](int buf) {
#pragma unroll
        for (int i = 0; i < 2; i++) {
            int f = tid * 2 + i;
            int row = f >> 2, c4 = (f & 3) * 4;
            float* d = &As[buf][row * AS_STRIDE + c4];
            d[0] = f2tf32(ar[i].x); d[1] = f2tf32(ar[i].y);
            d[2] = f2tf32(ar[i].z); d[3] = f2tf32(ar[i].w);
        }
    };
    auto loadB = [&](int k0) {
#pragma unroll
        for (int i = 0; i < 2; i++) {
            int f = tid * 2 + i;
            int row = f >> 5, c4 = (f & 31) * 4;
            int gc = colBase + c4;
            if (gc + 3 < N) {
                br[i] = *reinterpret_cast<const float4*>(&B[(size_t)(k0 + row) * N + gc]);
            } else {
                br[i].x = (gc + 0 < N) ? B[(size_t)(k0 + row) * N + gc + 0] : 0.f;
                br[i].y = (gc + 1 < N) ? B[(size_t)(k0 + row) * N + gc + 1] : 0.f;
                br[i].z = (gc + 2 < N) ? B[(size_t)(k0 + row) * N + gc + 2] : 0.f;
                br[i].w = 0.f;
            }
        }
    };
    auto storeB = [&](int buf) {
#pragma unroll
        for (int i = 0; i < 2; i++) {
            int f = tid * 2 + i;
            int row = f >> 5, c4 = (f & 31) * 4;
            float* d = &Bs[buf][row * BS_STRIDE + c4];
            d[0] = f2tf32(br[i].x); d[1] = f2tf32(br[i].y);
            d[2] = f2tf32(br[i].z); d[3] = f2tf32(br[i].w);
        }
    };

    loadA(0); loadB(0);
    storeA(0); storeB(0);
    __syncthreads();

    for (int kt = 0; kt < nk; kt++) {
        int buf = kt & 1;
        if (kt + 1 < nk) { loadA((kt + 1) << 4); loadB((kt + 1) << 4); }

#pragma unroll
        for (int ks = 0; ks < 2; ks++) {
            uint32_t bf[4][2];
#pragma unroll
            for (int nt = 0; nt < 4; nt++) {
                int n = warpN * 32 + nt * 8 + gid;
                bf[nt][0] = __float_as_uint(Bs[buf][(ks * 8 + tig) * BS_STRIDE + n]);
                bf[nt][1] = __float_as_uint(Bs[buf][(ks * 8 + tig + 4) * BS_STRIDE + n]);
            }
#pragma unroll
            for (int mt = 0; mt < 4; mt++) {
                int m = warpM * 64 + mt * 16;
                uint32_t af0 = __float_as_uint(As[buf][(m + gid) * AS_STRIDE + ks * 8 + tig]);
                uint32_t af1 = __float_as_uint(As[buf][(m + gid + 8) * AS_STRIDE + ks * 8 + tig]);
                uint32_t af2 = __float_as_uint(As[buf][(m + gid) * AS_STRIDE + ks * 8 + tig + 4]);
                uint32_t af3 = __float_as_uint(As[buf][(m + gid + 8) * AS_STRIDE + ks * 8 + tig + 4]);
#pragma unroll
                for (int nt = 0; nt < 4; nt++) {
                    asm volatile(
                        "mma.sync.aligned.m16n8k8.row.col.f32.tf32.tf32.f32 "
                        "{%0,%1,%2,%3}, {%4,%5,%6,%7}, {%8,%9}, {%0,%1,%2,%3};\n"
                        : "+f"(acc[mt][nt][0]), "+f"(acc[mt][nt][1]),
                          "+f"(acc[mt][nt][2]), "+f"(acc[mt][nt][3])
                        : "r"(af0), "r"(af1), "r"(af2), "r"(af3),
                          "r"(bf[nt][0]), "r"(bf[nt][1]));
                }
            }
        }

        if (kt + 1 < nk) { storeA(buf ^ 1); storeB(buf ^ 1); }
        __syncthreads();
    }

    // ---- epilogue ----
#pragma unroll
    for (int mt = 0; mt < 4; mt++) {
        int r0 = rowBase + warpM * 64 + mt * 16 + gid;
#pragma unroll
        for (int nt = 0; nt < 4; nt++) {
            int c0 = colBase + warpN * 32 + nt * 8 + tig * 2;
            if (c0 < N)     C[(size_t)r0 * N + c0]           = acc[mt][nt][0];
            if (c0 + 1 < N) C[(size_t)r0 * N + c0 + 1]       = acc[mt][nt][1];
            if (c0 < N)     C[(size_t)(r0 + 8) * N + c0]     = acc[mt][nt][2];
            if (c0 + 1 < N) C[(size_t)(r0 + 8) * N + c0 + 1] = acc[mt][nt][3];
        }
    }
}

// ---------------- conv1d (causal depthwise, K=4) + bias + silu ----------------
__global__ __launch_bounds__(256) void conv_kernel(const float* __restrict__ cw,
                                                   const float* __restrict__ cb) {
    int ch = blockIdx.x * 256 + threadIdx.x;   // < 1792
    int t  = blockIdx.y;
    int b  = t / LSEQ, l = t % LSEQ;
    float acc = cb[ch];
#pragma unroll
    for (int k = 0; k < KC; k++) {
        int lp = l - (KC - 1) + k;
        if (lp >= 0)
            acc = fmaf(g_zx[(size_t)(b * LSEQ + lp) * NPROJ + IF + ch], cw[k * XBCW + ch], acc);
    }
    acc = acc / (1.f + expf(-acc));   // silu
    g_xc[(size_t)t * XBCW + ch] = acc;
}

// ---------------- dt: softplus(dt_raw + bias), clip>=0 ----------------
__global__ __launch_bounds__(256) void dt_kernel(const float* __restrict__ dtb) {
    int idx = blockIdx.x * 256 + threadIdx.x;
    if (idx >= TTOT * HH) return;
    int t = idx / HH, h = idx % HH;
    float x = g_zx[(size_t)t * NPROJ + (NPROJ - HH) + h] + dtb[h];
    float sp = (x > 0.f) ? (x + log1pf(expf(-x))) : log1pf(expf(x));
    g_dt[idx] = fmaxf(sp, 0.f);
}

// ---------------- per-chunk inclusive cumsum of A*dt ----------------
__global__ __launch_bounds__(256) void acum_kernel(const float* __restrict__ alog) {
    int bx = blockIdx.x;                 // b*H*C blocks
    int c  = bx % CN;
    int h  = (bx / CN) % HH;
    int b  = bx / (CN * HH);
    int s  = threadIdx.x;
    int t  = b * LSEQ + c * CSZ + s;
    float A = -expf(alog[h]);
    __shared__ float a[CSZ];
    a[s] = A * g_dt[(size_t)t * HH + h];
    __syncthreads();
    for (int off = 1; off < CSZ; off <<= 1) {
        float add = (s >= off) ? a[s - off] : 0.f;
        __syncthreads();
        a[s] += add;
        __syncthreads();
    }
    g_ac[(size_t)((b * HH + h) * CN + c) * CSZ + s] = a[s];
}

// ---------------- local chunk state ----------------
__global__ __launch_bounds__(256) void chunkstate_kernel() {
    extern __shared__ float sm[];
    float* Bs = sm;               // 64 x 130
    float* Xs = sm + 64 * 130;    // 64 x 66
    int bx = blockIdx.x;
    int h = bx % HH;
    int c = (bx / HH) % CN;
    int b = bx / (HH * CN);
    int tid = threadIdx.x;
    int ty = tid >> 4, tx = tid & 15;
    int acbase = ((b * HH + h) * CN + c) * CSZ;
    float Asum = g_ac[acbase + CSZ - 1];
    float acc[4][8];
#pragma unroll
    for (int i = 0; i < 4; i++)
#pragma unroll
        for (int j = 0; j < 8; j++) acc[i][j] = 0.f;

    for (int lt = 0; lt < 4; lt++) {
        for (int i = tid; i < 64 * 128; i += 256) {
            int s = i >> 7, n = i & 127;
            int ts = b * LSEQ + c * CSZ + lt * 64 + s;
            float dec = expf(Asum - g_ac[acbase + lt * 64 + s]);
            Bs[s * 130 + n] = g_xc[(size_t)ts * XBCW + IF + n] * dec;
        }
        for (int i = tid; i < 64 * 64; i += 256) {
            int s = i >> 6, p = i & 63;
            int ts = b * LSEQ + c * CSZ + lt * 64 + s;
            Xs[s * 66 + p] = g_xc[(size_t)ts * XBCW + h * PP + p] * g_dt[(size_t)ts * HH + h];
        }
        __syncthreads();
        for (int s = 0; s < 64; s++) {
            float xv[4], bv[8];
#pragma unroll
            for (int i = 0; i < 4; i++) xv[i] = Xs[s * 66 + ty * 4 + i];
#pragma unroll
            for (int j = 0; j < 8; j++) bv[j] = Bs[s * 130 + tx * 8 + j];
#pragma unroll
            for (int i = 0; i < 4; i++)
#pragma unroll
                for (int j = 0; j < 8; j++) acc[i][j] = fmaf(xv[i], bv[j], acc[i][j]);
        }
        __syncthreads();
    }
    size_t base = ((size_t)((b * CN + c) * HH + h)) * PP * NST;
#pragma unroll
    for (int i = 0; i < 4; i++) {
        int p = ty * 4 + i;
#pragma unroll
        for (int j = 0; j < 8; j++) {
            int n = tx * 8 + j;
            g_ls[base + (size_t)p * NST + n] = acc[i][j];
        }
    }
}

// ---------------- inter-chunk recurrence over 16 chunks ----------------
__global__ __launch_bounds__(256) void recur_kernel() {
    int bh = blockIdx.x;   // 48
    int b = bh / HH, h = bh % HH;
    int tid = threadIdx.x;
    float st[32];
#pragma unroll
    for (int e = 0; e < 32; e++) st[e] = 0.f;
    for (int c = 0; c < CN; c++) {
        float es = expf(g_ac[(size_t)((b * HH + h) * CN + c) * CSZ + CSZ - 1]);
        size_t base = ((size_t)((b * CN + c) * HH + h)) * PP * NST;
#pragma unroll
        for (int e = 0; e < 32; e++) {
            int idx = tid + e * 256;
            g_ps[base + idx] = st[e];
            st[e] = fmaf(st[e], es, g_ls[base + idx]);
        }
    }
}

// ---------------- Y = (masked C B^T L) @ Xd  +  exp(Acum) * C @ S^T  +  D*x ----------------
__global__ __launch_bounds__(256) void ydiag_kernel(const float* __restrict__ Darr) {
    extern __shared__ float sm[];
    float* Cs = sm;                 // 64 x 130
    float* Bs = Cs + 64 * 130;      // 64 x 130  (B tiles, later S)
    float* Xs = Bs + 64 * 130;      // 64 x 66
    float* Gs = Xs + 64 * 66;       // 64 x 66
    float* aL = Gs + 64 * 66;       // 64
    float* aS = aL + 64;            // 64
    float* eA = aS + 64;            // 64

    int lt  = blockIdx.x;           // 0..3
    int bch = blockIdx.y;           // 768
    int h = bch % HH;
    int c = (bch / HH) % CN;
    int b = bch / (HH * CN);
    int tid = threadIdx.x;
    int ty = tid >> 4, tx = tid & 15;
    int acbase = ((b * HH + h) * CN + c) * CSZ;

    for (int i = tid; i < 64 * 128; i += 256) {
        int l = i >> 7, n = i & 127;
        int t = b * LSEQ + c * CSZ + lt * 64 + l;
        Cs[l * 130 + n] = g_xc[(size_t)t * XBCW + IF + NST + n];
    }
    if (tid < 64) aL[tid] = g_ac[acbase + lt * 64 + tid];

    float acc[4][4];
#pragma unroll
    for (int i = 0; i < 4; i++)
#pragma unroll
        for (int j = 0; j < 4; j++) acc[i][j] = 0.f;

    for (int st = 0; st <= lt; st++) {
        __syncthreads();
        for (int i = tid; i < 64 * 128; i += 256) {
            int s = i >> 7, n = i & 127;
            int ts = b * LSEQ + c * CSZ + st * 64 + s;
            Bs[s * 130 + n] = g_xc[(size_t)ts * XBCW + IF + n];
        }
        for (int i = tid; i < 64 * 64; i += 256) {
            int s = i >> 6, p = i & 63;
            int ts = b * LSEQ + c * CSZ + st * 64 + s;
            Xs[s * 66 + p] = g_xc[(size_t)ts * XBCW + h * PP + p] * g_dt[(size_t)ts * HH + h];
        }
        if (tid < 64) aS[tid] = g_ac[acbase + st * 64 + tid];
        __syncthreads();
        float g[4][4];
#pragma unroll
        for (int i = 0; i < 4; i++)
#pragma unroll
            for (int j = 0; j < 4; j++) g[i][j] = 0.f;
        for (int n = 0; n < 128; n++) {
            float cv[4], bv[4];
#pragma unroll
            for (int i = 0; i < 4; i++) cv[i] = Cs[(ty * 4 + i) * 130 + n];
#pragma unroll
            for (int j = 0; j < 4; j++) bv[j] = Bs[(tx * 4 + j) * 130 + n];
#pragma unroll
            for (int i = 0; i < 4; i++)
#pragma unroll
                for (int j = 0; j < 4; j++) g[i][j] = fmaf(cv[i], bv[j], g[i][j]);
        }
#pragma unroll
        for (int i = 0; i < 4; i++) {
            int gl = lt * 64 + ty * 4 + i;
#pragma unroll
            for (int j = 0; j < 4; j++) {
                int gs = st * 64 + tx * 4 + j;
                float f = (gs <= gl) ? expf(aL[ty * 4 + i] - aS[tx * 4 + j]) : 0.f;
                Gs[(ty * 4 + i) * 66 + (tx * 4 + j)] = g[i][j] * f;
            }
        }
        __syncthreads();
        for (int s = 0; s < 64; s++) {
            float gv[4], xv[4];
#pragma unroll
            for (int i = 0; i < 4; i++) gv[i] = Gs[(ty * 4 + i) * 66 + s];
#pragma unroll
            for (int j = 0; j < 4; j++) xv[j] = Xs[s * 66 + tx * 4 + j];
#pragma unroll
            for (int i = 0; i < 4; i++)
#pragma unroll
                for (int j = 0; j < 4; j++) acc[i][j] = fmaf(gv[i], xv[j], acc[i][j]);
        }
    }
    __syncthreads();
    {
        size_t base = ((size_t)((b * CN + c) * HH + h)) * PP * NST;
        for (int i = tid; i < 64 * 128; i += 256) {
            int p = i >> 7, n = i & 127;
            Bs[p * 130 + n] = g_ps[base + (size_t)p * NST + n];
        }
        if (tid < 64) eA[tid] = expf(aL[tid]);
        __syncthreads();
        float off[4][4];
#pragma unroll
        for (int i = 0; i < 4; i++)
#pragma unroll
            for (int j = 0; j < 4; j++) off[i][j] = 0.f;
        for (int n = 0; n < 128; n++) {
            float cv[4], sv[4];
#pragma unroll
            for (int i = 0; i < 4; i++) cv[i] = Cs[(ty * 4 + i) * 130 + n];
#pragma unroll
            for (int j = 0; j < 4; j++) sv[j] = Bs[(tx * 4 + j) * 130 + n];
#pragma unroll
            for (int i = 0; i < 4; i++)
#pragma unroll
                for (int j = 0; j < 4; j++) off[i][j] = fmaf(cv[i], sv[j], off[i][j]);
        }
#pragma unroll
        for (int i = 0; i < 4; i++)
#pragma unroll
            for (int j = 0; j < 4; j++) acc[i][j] += eA[ty * 4 + i] * off[i][j];
    }
    float Dh = Darr[h];
#pragma unroll
    for (int i = 0; i < 4; i++) {
        int t = b * LSEQ + c * CSZ + lt * 64 + ty * 4 + i;
#pragma unroll
        for (int j = 0; j < 4; j++) {
            int p = tx * 4 + j;
            float xraw = g_xc[(size_t)t * XBCW + h * PP + p];
            g_y[(size_t)t * IF + h * PP + p] = acc[i][j] + Dh * xraw;
        }
    }
}

// ---------------- gated RMSNorm (in-place on g_y) ----------------
__global__ __launch_bounds__(256) void gnorm_kernel(const float* __restrict__ nw) {
    int t = blockIdx.x;
    int tid = threadIdx.x;
    float vals[6];
    float ss = 0.f;
#pragma unroll
    for (int k = 0; k < 6; k++) {
        int i = tid + k * 256;
        float y = g_y[(size_t)t * IF + i];
        float z = g_zx[(size_t)t * NPROJ + i];
        float xf = y * (z / (1.f + expf(-z)));
        vals[k] = xf;
        ss += xf * xf;
    }
    __shared__ float red[256];
    __shared__ float s_scale;
    red[tid] = ss;
    __syncthreads();
    for (int o = 128; o > 0; o >>= 1) {
        if (tid < o) red[tid] += red[tid + o];
        __syncthreads();
    }
    if (tid == 0) s_scale = rsqrtf(red[0] / (float)IF + 1e-5f);
    __syncthreads();
    float sc = s_scale;
#pragma unroll
    for (int k = 0; k < 6; k++) {
        int i = tid + k * 256;
        g_y[(size_t)t * IF + i] = vals[k] * sc * nw[i];
    }
}

// ---------------- host launcher ----------------
extern "C" void kernel_launch(void* const* d_in, const int* in_sizes, int n_in,
                              void* d_out, int out_size) {
    const float* hs   = (const float*)d_in[0];
    const float* inw  = (const float*)d_in[1];
    const float* cw   = (const float*)d_in[2];
    const float* cb   = (const float*)d_in[3];
    const float* dtb  = (const float*)d_in[4];
    const float* alog = (const float*)d_in[5];
    const float* Dp   = (const float*)d_in[6];
    const float* nw   = (const float*)d_in[7];
    const float* ow   = (const float*)d_in[8];
    float* out = (float*)d_out;

    void *p_zx = nullptr, *p_y = nullptr;
    cudaGetSymbolAddress(&p_zx, g_zx);
    cudaGetSymbolAddress(&p_y, g_y);

    int smem_cs = (64 * 130 + 64 * 66) * 4;                       // 50176
    int smem_y  = (64 * 130 * 2 + 64 * 66 * 2 + 3 * 64) * 4;      // 101120
    cudaFuncSetAttribute(chunkstate_kernel, cudaFuncAttributeMaxDynamicSharedMemorySize, smem_cs);
    cudaFuncSetAttribute(ydiag_kernel, cudaFuncAttributeMaxDynamicSharedMemorySize, smem_y);

    // 1. in_proj GEMM (tf32 tensor cores): (8192 x 768) @ (768 x 3352)
    {
        dim3 grid((NPROJ + 127) / 128, TTOT / 128);
        tf32gemm_kernel<<<grid, 256>>>(hs, inw, (float*)p_zx, TTOT, NPROJ, HIDD);
    }
    // 2. conv + silu
    {
        dim3 grid(XBCW / 256, TTOT);
        conv_kernel<<<grid, 256>>>(cw, cb);
    }
    // 3. dt softplus
    dt_kernel<<<(TTOT * HH + 255) / 256, 256>>>(dtb);
    // 4. per-chunk cumsum of A*dt
    acum_kernel<<<BSZ * HH * CN, 256>>>(alog);
    // 5. local chunk states
    chunkstate_kernel<<<BSZ * CN * HH, 256, smem_cs>>>();
    // 6. inter-chunk recurrence
    recur_kernel<<<BSZ * HH, 256>>>();
    // 7. Y_diag + Y_off + D residual
    {
        dim3 grid(4, BSZ * CN * HH);
        ydiag_kernel<<<grid, 256, smem_y>>>(Dp);
    }
    // 8. gated RMSNorm
    gnorm_kernel<<<TTOT, 256>>>(nw);
    // 9. out_proj GEMM (tf32 tensor cores): (8192 x 1536) @ (1536 x 768) -> d_out
    {
        dim3 grid(HIDD / 128, TTOT / 128);
        tf32gemm_kernel<<<grid, 256>>>((const float*)p_y, ow, out, TTOT, HIDD, IF);
    }
}

// round 3
// speedup vs baseline: 2.1598x; 1.4435x over previous
#include <cuda_runtime.h>
#include <cuda_bf16.h>
#include <math.h>
#include <stdint.h>

// ---------------- problem constants ----------------
#define BSZ   2
#define LSEQ  4096
#define TTOT  8192          // BSZ*LSEQ
#define HIDD  768
#define IF    1536          // I
#define NST   128           // N
#define HH    24            // H
#define PP    64            // P
#define CSZ   256           // chunk size
#define CN    16            // LSEQ/CSZ
#define KC    4             // conv kernel
#define NPROJ 3352          // 2*(I+N)+H
#define XBCW  1792          // I+2N

// ---------------- scratch (static device globals; no allocs) ----------------
__device__ float g_zx[TTOT * NPROJ];               // in_proj output (z | xBC | dt)
__device__ float g_xc[TTOT * XBCW];                // conv+silu output
__device__ float g_dt[TTOT * HH];                  // softplus(dt+bias)
__device__ float g_ac[BSZ * HH * CN * CSZ];        // per-chunk inclusive cumsum of A*dt
__device__ float g_ls[BSZ * CN * HH * PP * NST];   // local chunk states  [b][c][h][p][n]
__device__ float g_ps[BSZ * CN * HH * PP * NST];   // prefix states entering chunk
__device__ float g_y [TTOT * IF];                  // y before / after gated norm (in-place)

// ---------------- helpers ----------------
__device__ __forceinline__ float f2tf32(float x) {
    uint32_t r;
    asm("cvt.rna.tf32.f32 %0, %1;" : "=r"(r) : "f"(x));
    return __uint_as_float(r);
}
__device__ __forceinline__ uint32_t fu(float x) { return __float_as_uint(x); }

__device__ __forceinline__ void mma_tf32(float* c, uint32_t a0, uint32_t a1,
                                         uint32_t a2, uint32_t a3,
                                         uint32_t b0, uint32_t b1) {
    asm volatile(
        "mma.sync.aligned.m16n8k8.row.col.f32.tf32.tf32.f32 "
        "{%0,%1,%2,%3}, {%4,%5,%6,%7}, {%8,%9}, {%0,%1,%2,%3};\n"
        : "+f"(c[0]), "+f"(c[1]), "+f"(c[2]), "+f"(c[3])
        : "r"(a0), "r"(a1), "r"(a2), "r"(a3), "r"(b0), "r"(b1));
}

// ================= TF32 tensor-core GEMM (projections) =================
#define AS_STRIDE 20     // 16 + 4 pad
#define BS_STRIDE 136    // 128 + 8 pad

__global__ __launch_bounds__(256) void tf32gemm_kernel(const float* __restrict__ A,
                                                       const float* __restrict__ B,
                                                       float* __restrict__ C,
                                                       int M, int N, int K) {
    __shared__ float As[2][128 * AS_STRIDE];
    __shared__ float Bs[2][16 * BS_STRIDE];

    const int tid   = threadIdx.x;
    const int lane  = tid & 31;
    const int warpId = tid >> 5;
    const int gid   = lane >> 2;
    const int tig   = lane & 3;
    const int warpM = warpId & 1;
    const int warpN = warpId >> 1;
    const int rowBase = blockIdx.y * 128;
    const int colBase = blockIdx.x * 128;

    float acc[4][4][4];
#pragma unroll
    for (int mt = 0; mt < 4; mt++)
#pragma unroll
        for (int nt = 0; nt < 4; nt++)
#pragma unroll
            for (int e = 0; e < 4; e++) acc[mt][nt][e] = 0.f;

    float4 ar[2], br[2];
    const int nk = K >> 4;

    auto loadA = [&](int k0) {
#pragma unroll
        for (int i = 0; i < 2; i++) {
            int f = tid * 2 + i;
            int row = f >> 2, c4 = (f & 3) * 4;
            ar[i] = *reinterpret_cast<const float4*>(&A[(size_t)(rowBase + row) * K + k0 + c4]);
        }
    };
    auto storeA = [&](int buf) {
#pragma unroll
        for (int i = 0; i < 2; i++) {
            int f = tid * 2 + i;
            int row = f >> 2, c4 = (f & 3) * 4;
            float* d = &As[buf][row * AS_STRIDE + c4];
            d[0] = f2tf32(ar[i].x); d[1] = f2tf32(ar[i].y);
            d[2] = f2tf32(ar[i].z); d[3] = f2tf32(ar[i].w);
        }
    };
    auto loadB = [&](int k0) {
#pragma unroll
        for (int i = 0; i < 2; i++) {
            int f = tid * 2 + i;
            int row = f >> 5, c4 = (f & 31) * 4;
            int gc = colBase + c4;
            if (gc + 3 < N) {
                br[i] = *reinterpret_cast<const float4*>(&B[(size_t)(k0 + row) * N + gc]);
            } else {
                br[i].x = (gc + 0 < N) ? B[(size_t)(k0 + row) * N + gc + 0] : 0.f;
                br[i].y = (gc + 1 < N) ? B[(size_t)(k0 + row) * N + gc + 1] : 0.f;
                br[i].z = (gc + 2 < N) ? B[(size_t)(k0 + row) * N + gc + 2] : 0.f;
                br[i].w = 0.f;
            }
        }
    };
    auto storeB = [&](int buf) {
#pragma unroll
        for (int i = 0; i < 2; i++) {
            int f = tid * 2 + i;
            int row = f >> 5, c4 = (f & 31) * 4;
            float* d = &Bs[buf][row * BS_STRIDE + c4];
            d[0] = f2tf32(br[i].x); d[1] = f2tf32(br[i].y);
            d[2] = f2tf32(br[i].z); d[3] = f2tf32(br[i].w);
        }
    };

    loadA(0); loadB(0);
    storeA(0); storeB(0);
    __syncthreads();

    for (int kt = 0; kt < nk; kt++) {
        int buf = kt & 1;
        if (kt + 1 < nk) { loadA((kt + 1) << 4); loadB((kt + 1) << 4); }

#pragma unroll
        for (int ks = 0; ks < 2; ks++) {
            uint32_t bf[4][2];
#pragma unroll
            for (int nt = 0; nt < 4; nt++) {
                int n = warpN * 32 + nt * 8 + gid;
                bf[nt][0] = fu(Bs[buf][(ks * 8 + tig) * BS_STRIDE + n]);
                bf[nt][1] = fu(Bs[buf][(ks * 8 + tig + 4) * BS_STRIDE + n]);
            }
#pragma unroll
            for (int mt = 0; mt < 4; mt++) {
                int m = warpM * 64 + mt * 16;
                uint32_t af0 = fu(As[buf][(m + gid) * AS_STRIDE + ks * 8 + tig]);
                uint32_t af1 = fu(As[buf][(m + gid + 8) * AS_STRIDE + ks * 8 + tig]);
                uint32_t af2 = fu(As[buf][(m + gid) * AS_STRIDE + ks * 8 + tig + 4]);
                uint32_t af3 = fu(As[buf][(m + gid + 8) * AS_STRIDE + ks * 8 + tig + 4]);
#pragma unroll
                for (int nt = 0; nt < 4; nt++)
                    mma_tf32(acc[mt][nt], af0, af1, af2, af3, bf[nt][0], bf[nt][1]);
            }
        }

        if (kt + 1 < nk) { storeA(buf ^ 1); storeB(buf ^ 1); }
        __syncthreads();
    }

#pragma unroll
    for (int mt = 0; mt < 4; mt++) {
        int r0 = rowBase + warpM * 64 + mt * 16 + gid;
#pragma unroll
        for (int nt = 0; nt < 4; nt++) {
            int c0 = colBase + warpN * 32 + nt * 8 + tig * 2;
            if (c0 < N)     C[(size_t)r0 * N + c0]           = acc[mt][nt][0];
            if (c0 + 1 < N) C[(size_t)r0 * N + c0 + 1]       = acc[mt][nt][1];
            if (c0 < N)     C[(size_t)(r0 + 8) * N + c0]     = acc[mt][nt][2];
            if (c0 + 1 < N) C[(size_t)(r0 + 8) * N + c0 + 1] = acc[mt][nt][3];
        }
    }
}

// ---------------- conv1d (causal depthwise, K=4) + bias + silu ----------------
__global__ __launch_bounds__(256) void conv_kernel(const float* __restrict__ cw,
                                                   const float* __restrict__ cb) {
    int ch = blockIdx.x * 256 + threadIdx.x;
    int t  = blockIdx.y;
    int b  = t / LSEQ, l = t % LSEQ;
    float acc = cb[ch];
#pragma unroll
    for (int k = 0; k < KC; k++) {
        int lp = l - (KC - 1) + k;
        if (lp >= 0)
            acc = fmaf(g_zx[(size_t)(b * LSEQ + lp) * NPROJ + IF + ch], cw[k * XBCW + ch], acc);
    }
    acc = acc / (1.f + expf(-acc));
    g_xc[(size_t)t * XBCW + ch] = acc;
}

// ---------------- dt: softplus(dt_raw + bias), clip>=0 ----------------
__global__ __launch_bounds__(256) void dt_kernel(const float* __restrict__ dtb) {
    int idx = blockIdx.x * 256 + threadIdx.x;
    if (idx >= TTOT * HH) return;
    int t = idx / HH, h = idx % HH;
    float x = g_zx[(size_t)t * NPROJ + (NPROJ - HH) + h] + dtb[h];
    float sp = (x > 0.f) ? (x + log1pf(expf(-x))) : log1pf(expf(x));
    g_dt[idx] = fmaxf(sp, 0.f);
}

// ---------------- per-chunk inclusive cumsum of A*dt ----------------
__global__ __launch_bounds__(256) void acum_kernel(const float* __restrict__ alog) {
    int bx = blockIdx.x;
    int c  = bx % CN;
    int h  = (bx / CN) % HH;
    int b  = bx / (CN * HH);
    int s  = threadIdx.x;
    int t  = b * LSEQ + c * CSZ + s;
    float A = -expf(alog[h]);
    __shared__ float a[CSZ];
    a[s] = A * g_dt[(size_t)t * HH + h];
    __syncthreads();
    for (int off = 1; off < CSZ; off <<= 1) {
        float add = (s >= off) ? a[s - off] : 0.f;
        __syncthreads();
        a[s] += add;
        __syncthreads();
    }
    g_ac[(size_t)((b * HH + h) * CN + c) * CSZ + s] = a[s];
}

// ================= chunk state via TF32 mma =================
// S[p][n] (64x128) = sum_l Xd^T[p][l] * decB[l][n],  K = 256 in 4 tiles of 64.
// 8 warps: warpM (2) x warpN (4); warp tile 32(p) x 32(n); mt=2, nt=4.
#define CS_AS 68    // 64 + 4  (A-operand: banks gid*4+tig)
#define CS_BS 136   // 128 + 8 (B-operand: banks tig*8+gid)

__global__ __launch_bounds__(256) void chunkstate_mma_kernel() {
    extern __shared__ float sm[];
    float* As = sm;                 // 64 x CS_AS  (A[p][l] = x*dt transposed)
    float* Bs = sm + 64 * CS_AS;    // 64 x CS_BS  (decB[l][n])

    int bx = blockIdx.x;
    int h = bx % HH;
    int c = (bx / HH) % CN;
    int b = bx / (HH * CN);
    int tid = threadIdx.x, lane = tid & 31, warpId = tid >> 5;
    int gid = lane >> 2, tig = lane & 3;
    int warpM = warpId & 1, warpN = warpId >> 1;
    int acbase = ((b * HH + h) * CN + c) * CSZ;
    int tbase = b * LSEQ + c * CSZ;
    float Asum = g_ac[acbase + CSZ - 1];

    float acc[2][4][4];
#pragma unroll
    for (int mt = 0; mt < 2; mt++)
#pragma unroll
        for (int nt = 0; nt < 4; nt++)
#pragma unroll
            for (int e = 0; e < 4; e++) acc[mt][nt][e] = 0.f;

    for (int kt = 0; kt < 4; kt++) {
        // A: Xd transposed [p][l]
        for (int i = tid; i < 64 * 64; i += 256) {
            int l = i >> 6, p = i & 63;
            int ts = tbase + kt * 64 + l;
            float v = g_xc[(size_t)ts * XBCW + h * PP + p] * g_dt[(size_t)ts * HH + h];
            As[p * CS_AS + l] = f2tf32(v);
        }
        // B: decayed B [l][n]
        for (int i = tid; i < 64 * 128; i += 256) {
            int l = i >> 7, n = i & 127;
            int ts = tbase + kt * 64 + l;
            float dec = expf(Asum - g_ac[acbase + kt * 64 + l]);
            Bs[l * CS_BS + n] = f2tf32(g_xc[(size_t)ts * XBCW + IF + n] * dec);
        }
        __syncthreads();
#pragma unroll
        for (int k8 = 0; k8 < 8; k8++) {
            int k0 = k8 * 8;
            uint32_t af[2][4];
#pragma unroll
            for (int mt = 0; mt < 2; mt++) {
                int m = warpM * 32 + mt * 16;
                af[mt][0] = fu(As[(m + gid) * CS_AS + k0 + tig]);
                af[mt][1] = fu(As[(m + gid + 8) * CS_AS + k0 + tig]);
                af[mt][2] = fu(As[(m + gid) * CS_AS + k0 + tig + 4]);
                af[mt][3] = fu(As[(m + gid + 8) * CS_AS + k0 + tig + 4]);
            }
#pragma unroll
            for (int nt = 0; nt < 4; nt++) {
                int n = warpN * 32 + nt * 8 + gid;
                uint32_t b0 = fu(Bs[(k0 + tig) * CS_BS + n]);
                uint32_t b1 = fu(Bs[(k0 + tig + 4) * CS_BS + n]);
#pragma unroll
                for (int mt = 0; mt < 2; mt++)
                    mma_tf32(acc[mt][nt], af[mt][0], af[mt][1], af[mt][2], af[mt][3], b0, b1);
            }
        }
        __syncthreads();
    }

    size_t base = ((size_t)((b * CN + c) * HH + h)) * PP * NST;
#pragma unroll
    for (int mt = 0; mt < 2; mt++) {
        int p0 = warpM * 32 + mt * 16 + gid;
#pragma unroll
        for (int nt = 0; nt < 4; nt++) {
            int n0 = warpN * 32 + nt * 8 + tig * 2;
            g_ls[base + (size_t)p0 * NST + n0]           = acc[mt][nt][0];
            g_ls[base + (size_t)p0 * NST + n0 + 1]       = acc[mt][nt][1];
            g_ls[base + (size_t)(p0 + 8) * NST + n0]     = acc[mt][nt][2];
            g_ls[base + (size_t)(p0 + 8) * NST + n0 + 1] = acc[mt][nt][3];
        }
    }
}

// ---------------- inter-chunk recurrence over 16 chunks ----------------
__global__ __launch_bounds__(256) void recur_kernel() {
    int bh = blockIdx.x;
    int b = bh / HH, h = bh % HH;
    int tid = threadIdx.x;
    float st[32];
#pragma unroll
    for (int e = 0; e < 32; e++) st[e] = 0.f;
    for (int c = 0; c < CN; c++) {
        float es = expf(g_ac[(size_t)((b * HH + h) * CN + c) * CSZ + CSZ - 1]);
        size_t base = ((size_t)((b * CN + c) * HH + h)) * PP * NST;
#pragma unroll
        for (int e = 0; e < 32; e++) {
            int idx = tid + e * 256;
            g_ps[base + idx] = st[e];
            st[e] = fmaf(st[e], es, g_ls[base + idx]);
        }
    }
}

// ================= Y via TF32 mma =================
// Per (lt, b,c,h): out tile 64(l) x 64(p).
// G = C_lt (64x128) @ B_st^T  -> mask/decay in regs -> Gs; acc += Gs @ Xd_st.
// Off: acc += exp(aL) * (C_lt @ S^T).
// 8 warps: warpM (4, l) x warpN (2, cols); warp tile 16 x 32; nt=4.
#define YD_CS 132   // C / Bst / Ss stride (A & col-strided B reads: banks *4)
#define YD_XS 72    // Xs stride (row-strided B reads: banks *8)
#define YD_GS 68    // Gs stride (A reads: banks *4)

__global__ __launch_bounds__(256) void ydiag_mma_kernel(const float* __restrict__ Darr) {
    extern __shared__ float sm[];
    float* Cs  = sm;                   // 64 x 132
    float* Bst = Cs + 64 * YD_CS;      // 64 x 132 (B tiles, later S)
    float* Xs  = Bst + 64 * YD_CS;     // 64 x 72
    float* Gs  = Xs + 64 * YD_XS;      // 64 x 68
    float* aL  = Gs + 64 * YD_GS;      // 64
    float* aS  = aL + 64;              // 64

    int lt  = blockIdx.x;
    int bch = blockIdx.y;
    int h = bch % HH;
    int c = (bch / HH) % CN;
    int b = bch / (HH * CN);
    int tid = threadIdx.x, lane = tid & 31, warpId = tid >> 5;
    int gid = lane >> 2, tig = lane & 3;
    int m0 = (warpId & 3) * 16;        // l rows of this warp
    int n0 = (warpId >> 2) * 32;       // col base (s or p)
    int acbase = ((b * HH + h) * CN + c) * CSZ;
    int tbase = b * LSEQ + c * CSZ;

    for (int i = tid; i < 64 * 128; i += 256) {
        int l = i >> 7, n = i & 127;
        Cs[l * YD_CS + n] = f2tf32(g_xc[(size_t)(tbase + lt * 64 + l) * XBCW + IF + NST + n]);
    }
    if (tid < 64) aL[tid] = g_ac[acbase + lt * 64 + tid];

    float accD[4][4];
#pragma unroll
    for (int nt = 0; nt < 4; nt++)
#pragma unroll
        for (int e = 0; e < 4; e++) accD[nt][e] = 0.f;

    for (int st = 0; st <= lt; st++) {
        __syncthreads();   // previous iteration's consumers done (uniform barrier seq)
        for (int i = tid; i < 64 * 128; i += 256) {
            int s = i >> 7, n = i & 127;
            Bst[s * YD_CS + n] = f2tf32(g_xc[(size_t)(tbase + st * 64 + s) * XBCW + IF + n]);
        }
        for (int i = tid; i < 64 * 64; i += 256) {
            int s = i >> 6, p = i & 63;
            int ts = tbase + st * 64 + s;
            Xs[s * YD_XS + p] = f2tf32(g_xc[(size_t)ts * XBCW + h * PP + p] * g_dt[(size_t)ts * HH + h]);
        }
        if (tid < 64) aS[tid] = g_ac[acbase + st * 64 + tid];
        __syncthreads();

        // ---- G = C @ B^T (K = 128) ----
        float g4[4][4];
#pragma unroll
        for (int nt = 0; nt < 4; nt++)
#pragma unroll
            for (int e = 0; e < 4; e++) g4[nt][e] = 0.f;
#pragma unroll
        for (int k8 = 0; k8 < 16; k8++) {
            int k0 = k8 * 8;
            uint32_t a0 = fu(Cs[(m0 + gid) * YD_CS + k0 + tig]);
            uint32_t a1 = fu(Cs[(m0 + gid + 8) * YD_CS + k0 + tig]);
            uint32_t a2 = fu(Cs[(m0 + gid) * YD_CS + k0 + tig + 4]);
            uint32_t a3 = fu(Cs[(m0 + gid + 8) * YD_CS + k0 + tig + 4]);
#pragma unroll
            for (int nt = 0; nt < 4; nt++) {
                int s = n0 + nt * 8 + gid;   // column index of G = source position
                uint32_t b0 = fu(Bst[s * YD_CS + k0 + tig]);
                uint32_t b1 = fu(Bst[s * YD_CS + k0 + tig + 4]);
                mma_tf32(g4[nt], a0, a1, a2, a3, b0, b1);
            }
        }
        // ---- mask + decay in registers, spill masked G to smem ----
        {
            int lA = m0 + gid, lB = lA + 8;
            int glA = lt * 64 + lA, glB = glA + 8;
            float aLA = aL[lA], aLB = aL[lB];
#pragma unroll
            for (int nt = 0; nt < 4; nt++) {
                int s0 = n0 + nt * 8 + tig * 2;
                int gs0 = st * 64 + s0;
                float as0 = aS[s0], as1 = aS[s0 + 1];
                float v0 = (gs0     <= glA) ? g4[nt][0] * expf(aLA - as0) : 0.f;
                float v1 = (gs0 + 1 <= glA) ? g4[nt][1] * expf(aLA - as1) : 0.f;
                float v2 = (gs0     <= glB) ? g4[nt][2] * expf(aLB - as0) : 0.f;
                float v3 = (gs0 + 1 <= glB) ? g4[nt][3] * expf(aLB - as1) : 0.f;
                Gs[lA * YD_GS + s0]     = f2tf32(v0);
                Gs[lA * YD_GS + s0 + 1] = f2tf32(v1);
                Gs[lB * YD_GS + s0]     = f2tf32(v2);
                Gs[lB * YD_GS + s0 + 1] = f2tf32(v3);
            }
        }
        __syncthreads();
        // ---- acc += G @ Xd (K = 64) ----
#pragma unroll
        for (int k8 = 0; k8 < 8; k8++) {
            int k0 = k8 * 8;
            uint32_t a0 = fu(Gs[(m0 + gid) * YD_GS + k0 + tig]);
            uint32_t a1 = fu(Gs[(m0 + gid + 8) * YD_GS + k0 + tig]);
            uint32_t a2 = fu(Gs[(m0 + gid) * YD_GS + k0 + tig + 4]);
            uint32_t a3 = fu(Gs[(m0 + gid + 8) * YD_GS + k0 + tig + 4]);
#pragma unroll
            for (int nt = 0; nt < 4; nt++) {
                int p = n0 + nt * 8 + gid;
                uint32_t b0 = fu(Xs[(k0 + tig) * YD_XS + p]);
                uint32_t b1 = fu(Xs[(k0 + tig + 4) * YD_XS + p]);
                mma_tf32(accD[nt], a0, a1, a2, a3, b0, b1);
            }
        }
    }

    // ---- off part: off = C @ S^T (K = 128), acc += exp(aL) * off ----
    __syncthreads();
    {
        size_t sbase = ((size_t)((b * CN + c) * HH + h)) * PP * NST;
        for (int i = tid; i < 64 * 128; i += 256) {
            int p = i >> 7, n = i & 127;
            Bst[p * YD_CS + n] = f2tf32(g_ps[sbase + (size_t)p * NST + n]);
        }
    }
    __syncthreads();
    float off4[4][4];
#pragma unroll
    for (int nt = 0; nt < 4; nt++)
#pragma unroll
        for (int e = 0; e < 4; e++) off4[nt][e] = 0.f;
#pragma unroll
    for (int k8 = 0; k8 < 16; k8++) {
        int k0 = k8 * 8;
        uint32_t a0 = fu(Cs[(m0 + gid) * YD_CS + k0 + tig]);
        uint32_t a1 = fu(Cs[(m0 + gid + 8) * YD_CS + k0 + tig]);
        uint32_t a2 = fu(Cs[(m0 + gid) * YD_CS + k0 + tig + 4]);
        uint32_t a3 = fu(Cs[(m0 + gid + 8) * YD_CS + k0 + tig + 4]);
#pragma unroll
        for (int nt = 0; nt < 4; nt++) {
            int p = n0 + nt * 8 + gid;
            uint32_t b0 = fu(Bst[p * YD_CS + k0 + tig]);
            uint32_t b1 = fu(Bst[p * YD_CS + k0 + tig + 4]);
            mma_tf32(off4[nt], a0, a1, a2, a3, b0, b1);
        }
    }

    // ---- epilogue: y = accD + exp(aL)*off + D*x ----
    {
        int lA = m0 + gid, lB = lA + 8;
        float e0 = expf(aL[lA]), e1 = expf(aL[lB]);
        float Dh = Darr[h];
        int tA = tbase + lt * 64 + lA;
        int tB = tbase + lt * 64 + lB;
#pragma unroll
        for (int nt = 0; nt < 4; nt++) {
            int p0 = n0 + nt * 8 + tig * 2;
            float xA0 = g_xc[(size_t)tA * XBCW + h * PP + p0];
            float xA1 = g_xc[(size_t)tA * XBCW + h * PP + p0 + 1];
            float xB0 = g_xc[(size_t)tB * XBCW + h * PP + p0];
            float xB1 = g_xc[(size_t)tB * XBCW + h * PP + p0 + 1];
            g_y[(size_t)tA * IF + h * PP + p0]     = accD[nt][0] + e0 * off4[nt][0] + Dh * xA0;
            g_y[(size_t)tA * IF + h * PP + p0 + 1] = accD[nt][1] + e0 * off4[nt][1] + Dh * xA1;
            g_y[(size_t)tB * IF + h * PP + p0]     = accD[nt][2] + e1 * off4[nt][2] + Dh * xB0;
            g_y[(size_t)tB * IF + h * PP + p0 + 1] = accD[nt][3] + e1 * off4[nt][3] + Dh * xB1;
        }
    }
}

// ---------------- gated RMSNorm (in-place on g_y) ----------------
__global__ __launch_bounds__(256) void gnorm_kernel(const float* __restrict__ nw) {
    int t = blockIdx.x;
    int tid = threadIdx.x;
    float vals[6];
    float ss = 0.f;
#pragma unroll
    for (int k = 0; k < 6; k++) {
        int i = tid + k * 256;
        float y = g_y[(size_t)t * IF + i];
        float z = g_zx[(size_t)t * NPROJ + i];
        float xf = y * (z / (1.f + expf(-z)));
        vals[k] = xf;
        ss += xf * xf;
    }
    __shared__ float red[256];
    __shared__ float s_scale;
    red[tid] = ss;
    __syncthreads();
    for (int o = 128; o > 0; o >>= 1) {
        if (tid < o) red[tid] += red[tid + o];
        __syncthreads();
    }
    if (tid == 0) s_scale = rsqrtf(red[0] / (float)IF + 1e-5f);
    __syncthreads();
    float sc = s_scale;
#pragma unroll
    for (int k = 0; k < 6; k++) {
        int i = tid + k * 256;
        g_y[(size_t)t * IF + i] = vals[k] * sc * nw[i];
    }
}

// ---------------- host launcher ----------------
extern "C" void kernel_launch(void* const* d_in, const int* in_sizes, int n_in,
                              void* d_out, int out_size) {
    const float* hs   = (const float*)d_in[0];
    const float* inw  = (const float*)d_in[1];
    const float* cw   = (const float*)d_in[2];
    const float* cb   = (const float*)d_in[3];
    const float* dtb  = (const float*)d_in[4];
    const float* alog = (const float*)d_in[5];
    const float* Dp   = (const float*)d_in[6];
    const float* nw   = (const float*)d_in[7];
    const float* ow   = (const float*)d_in[8];
    float* out = (float*)d_out;

    void *p_zx = nullptr, *p_y = nullptr;
    cudaGetSymbolAddress(&p_zx, g_zx);
    cudaGetSymbolAddress(&p_y, g_y);

    int smem_cs = (64 * CS_AS + 64 * CS_BS) * 4;                              // ~52KB
    int smem_y  = (64 * YD_CS * 2 + 64 * YD_XS + 64 * YD_GS + 128) * 4;       // ~104KB
    cudaFuncSetAttribute(chunkstate_mma_kernel, cudaFuncAttributeMaxDynamicSharedMemorySize, smem_cs);
    cudaFuncSetAttribute(ydiag_mma_kernel, cudaFuncAttributeMaxDynamicSharedMemorySize, smem_y);

    // 1. in_proj GEMM (tf32): (8192 x 768) @ (768 x 3352)
    {
        dim3 grid((NPROJ + 127) / 128, TTOT / 128);
        tf32gemm_kernel<<<grid, 256>>>(hs, inw, (float*)p_zx, TTOT, NPROJ, HIDD);
    }
    // 2. conv + silu
    {
        dim3 grid(XBCW / 256, TTOT);
        conv_kernel<<<grid, 256>>>(cw, cb);
    }
    // 3. dt softplus
    dt_kernel<<<(TTOT * HH + 255) / 256, 256>>>(dtb);
    // 4. per-chunk cumsum of A*dt
    acum_kernel<<<BSZ * HH * CN, 256>>>(alog);
    // 5. local chunk states (tf32 mma)
    chunkstate_mma_kernel<<<BSZ * CN * HH, 256, smem_cs>>>();
    // 6. inter-chunk recurrence
    recur_kernel<<<BSZ * HH, 256>>>();
    // 7. Y_diag + Y_off + D residual (tf32 mma)
    {
        dim3 grid(4, BSZ * CN * HH);
        ydiag_mma_kernel<<<grid, 256, smem_y>>>(Dp);
    }
    // 8. gated RMSNorm
    gnorm_kernel<<<TTOT, 256>>>(nw);
    // 9. out_proj GEMM (tf32): (8192 x 1536) @ (1536 x 768) -> d_out
    {
        dim3 grid(HIDD / 128, TTOT / 128);
        tf32gemm_kernel<<<grid, 256>>>((const float*)p_y, ow, out, TTOT, HIDD, IF);
    }
}

// round 4
// speedup vs baseline: 2.5551x; 1.1830x over previous
#include <cuda_runtime.h>
#include <cuda_bf16.h>
#include <math.h>
#include <stdint.h>

// ---------------- problem constants ----------------
#define BSZ   2
#define LSEQ  4096
#define TTOT  8192          // BSZ*LSEQ
#define HIDD  768
#define IF    1536          // I
#define NST   128           // N
#define HH    24            // H
#define PP    64            // P
#define CSZ   256           // chunk size
#define CN    16            // LSEQ/CSZ
#define KC    4             // conv kernel
#define NPROJ 3352          // 2*(I+N)+H
#define XBCW  1792          // I+2N

// ---------------- scratch (static device globals; no allocs) ----------------
__device__ float g_zx[TTOT * NPROJ];               // in_proj output (z | xBC | dt)
__device__ float g_xc[TTOT * XBCW];                // conv+silu output
__device__ float g_dt[TTOT * HH];                  // softplus(dt+bias)
__device__ float g_ac[BSZ * HH * CN * CSZ];        // per-chunk inclusive cumsum of A*dt
__device__ float g_ls[BSZ * CN * HH * PP * NST];   // local chunk states
__device__ float g_ps[BSZ * CN * HH * PP * NST];   // prefix states entering chunk
__device__ float g_y [TTOT * IF];                  // y (tf32-rounded after gnorm)
__device__ float g_hsr [TTOT * HIDD];              // hs rounded to tf32
__device__ float g_inwT[NPROJ * HIDD];             // in_proj_w^T, tf32
__device__ float g_owT [HIDD * IF];                // out_proj_w^T, tf32

// ---------------- helpers ----------------
__device__ __forceinline__ float f2tf32(float x) {
    uint32_t r;
    asm("cvt.rna.tf32.f32 %0, %1;" : "=r"(r) : "f"(x));
    return __uint_as_float(r);
}
__device__ __forceinline__ uint32_t fu(float x) { return __float_as_uint(x); }

__device__ __forceinline__ void mma_tf32(float* c, uint32_t a0, uint32_t a1,
                                         uint32_t a2, uint32_t a3,
                                         uint32_t b0, uint32_t b1) {
    asm volatile(
        "mma.sync.aligned.m16n8k8.row.col.f32.tf32.tf32.f32 "
        "{%0,%1,%2,%3}, {%4,%5,%6,%7}, {%8,%9}, {%0,%1,%2,%3};\n"
        : "+f"(c[0]), "+f"(c[1]), "+f"(c[2]), "+f"(c[3])
        : "r"(a0), "r"(a1), "r"(a2), "r"(a3), "r"(b0), "r"(b1));
}
__device__ __forceinline__ void ldsm_x4(uint32_t addr, uint32_t& r0, uint32_t& r1,
                                        uint32_t& r2, uint32_t& r3) {
    asm volatile("ldmatrix.sync.aligned.m8n8.x4.shared.b16 {%0,%1,%2,%3}, [%4];"
                 : "=r"(r0), "=r"(r1), "=r"(r2), "=r"(r3) : "r"(addr));
}
__device__ __forceinline__ void cpasync16(uint32_t daddr, const void* gaddr, bool pred) {
    int sz = pred ? 16 : 0;
    asm volatile("cp.async.cg.shared.global [%0], [%1], 16, %2;"
                 :: "r"(daddr), "l"(gaddr), "r"(sz));
}
#define CP_COMMIT()  asm volatile("cp.async.commit_group;")
#define CP_WAIT1()   asm volatile("cp.async.wait_group 1;")

// ================= TF32 GEMM: ldmatrix + cp.async 3-stage =================
// C = A(MxK) @ Bt^T where Bt is [N][K] row-major, both pre-rounded tf32.
// BM=BN=128, BK=16, 256 thr = 8 warps (warpM 2 x warpN 4), warp tile 64x32.
// smem per stage: A 128x20, B 128x20 floats (stride 20 = conflict-free ldmatrix).
#define GST 20               // row stride (floats)
#define STAGE_F (128 * GST)  // floats per matrix per stage

__global__ __launch_bounds__(256) void tf32gemm_ldsm_kernel(const float* __restrict__ A,
                                                            const float* __restrict__ Bt,
                                                            float* __restrict__ C,
                                                            int M, int N, int K) {
    extern __shared__ float sm[];
    const int tid = threadIdx.x;
    const int lane = tid & 31;
    const int warpId = tid >> 5;
    const int gid = lane >> 2, tig = lane & 3;
    const int warpM = warpId & 1;
    const int warpN = warpId >> 1;
    const int rowBase = blockIdx.y * 128;
    const int colBase = blockIdx.x * 128;
    const int nk = K >> 4;

    uint32_t smBase = (uint32_t)__cvta_generic_to_shared(sm);

    // cp.async per-thread assignment: row r, chunks cb, cb+1 (16B each)
    const int cpr = tid >> 1;
    const int cpc = (tid & 1) * 2;
    const int nB = colBase + cpr;
    const bool bOK = nB < N;
    const int nBc = bOK ? nB : 0;
    const uint32_t cpAoff = (uint32_t)(cpr * GST + cpc * 4) * 4;
    const uint32_t cpBoff = cpAoff;

    auto issue = [&](int kt, int stage) {
        int k0 = kt << 4;
        uint32_t sA = smBase + (uint32_t)(stage * 2 * STAGE_F) * 4 + cpAoff;
        uint32_t sB = smBase + (uint32_t)((stage * 2 + 1) * STAGE_F) * 4 + cpBoff;
        const float* ga = &A[(size_t)(rowBase + cpr) * K + k0 + cpc * 4];
        const float* gb = &Bt[(size_t)nBc * K + k0 + cpc * 4];
        cpasync16(sA, ga, true);
        cpasync16(sA + 16, ga + 4, true);
        cpasync16(sB, gb, bOK);
        cpasync16(sB + 16, gb + 4, bOK);
        CP_COMMIT();
    };

    // ldmatrix per-lane offsets (floats within tile)
    const uint32_t aLaneOff = (uint32_t)((lane & 15) * GST + (lane >> 4) * 4);
    const uint32_t bLaneOff = (uint32_t)(((lane >> 4) * 8 + (lane & 7)) * GST + ((lane >> 3) & 1) * 4);

    float acc[4][4][4];
#pragma unroll
    for (int mt = 0; mt < 4; mt++)
#pragma unroll
        for (int nt = 0; nt < 4; nt++)
#pragma unroll
            for (int e = 0; e < 4; e++) acc[mt][nt][e] = 0.f;

    issue(0, 0);
    if (nk > 1) issue(1, 1);

    for (int kt = 0; kt < nk; kt++) {
        CP_WAIT1();
        __syncthreads();
        if (kt + 2 < nk) issue(kt + 2, (kt + 2) % 3);

        int stage = kt % 3;
        uint32_t aBase = smBase + (uint32_t)(stage * 2 * STAGE_F) * 4;
        uint32_t bBase = smBase + (uint32_t)((stage * 2 + 1) * STAGE_F) * 4;

#pragma unroll
        for (int ks = 0; ks < 2; ks++) {
            uint32_t bfr[4][2];
#pragma unroll
            for (int pair = 0; pair < 2; pair++) {
                uint32_t addr = bBase + ((uint32_t)((warpN * 32 + pair * 16) * GST + ks * 8) + bLaneOff) * 4;
                uint32_t r0, r1, r2, r3;
                ldsm_x4(addr, r0, r1, r2, r3);
                bfr[pair * 2][0] = r0; bfr[pair * 2][1] = r1;
                bfr[pair * 2 + 1][0] = r2; bfr[pair * 2 + 1][1] = r3;
            }
#pragma unroll
            for (int mt = 0; mt < 4; mt++) {
                uint32_t addr = aBase + ((uint32_t)((warpM * 64 + mt * 16) * GST + ks * 8) + aLaneOff) * 4;
                uint32_t a0, a1, a2, a3;
                ldsm_x4(addr, a0, a1, a2, a3);
#pragma unroll
                for (int nt = 0; nt < 4; nt++)
                    mma_tf32(acc[mt][nt], a0, a1, a2, a3, bfr[nt][0], bfr[nt][1]);
            }
        }
    }

    // epilogue
#pragma unroll
    for (int mt = 0; mt < 4; mt++) {
        int r0 = rowBase + warpM * 64 + mt * 16 + gid;
#pragma unroll
        for (int nt = 0; nt < 4; nt++) {
            int c0 = colBase + warpN * 32 + nt * 8 + tig * 2;
            if (c0 < N)     C[(size_t)r0 * N + c0]           = acc[mt][nt][0];
            if (c0 + 1 < N) C[(size_t)r0 * N + c0 + 1]       = acc[mt][nt][1];
            if (c0 < N)     C[(size_t)(r0 + 8) * N + c0]     = acc[mt][nt][2];
            if (c0 + 1 < N) C[(size_t)(r0 + 8) * N + c0 + 1] = acc[mt][nt][3];
        }
    }
}

// ---------------- prep: round / transpose+round ----------------
__global__ __launch_bounds__(256) void round_kernel(const float* __restrict__ src,
                                                    float* __restrict__ dst, int n) {
    int i = blockIdx.x * 256 + threadIdx.x;
    if (i < n) dst[i] = f2tf32(src[i]);
}

__global__ void transpose_round_kernel(const float* __restrict__ src,
                                       float* __restrict__ dst, int R, int Cc) {
    // src [R][Cc] -> dst [Cc][R], rounded to tf32
    __shared__ float t[32][33];
    int c0 = blockIdx.x * 32, r0 = blockIdx.y * 32;
    int x = c0 + threadIdx.x;
    for (int i = threadIdx.y; i < 32; i += 8) {
        int y = r0 + i;
        if (x < Cc && y < R) t[i][threadIdx.x] = src[(size_t)y * Cc + x];
    }
    __syncthreads();
    int xo = r0 + threadIdx.x;
    for (int i = threadIdx.y; i < 32; i += 8) {
        int yo = c0 + i;
        if (xo < R && yo < Cc) dst[(size_t)yo * R + xo] = f2tf32(t[threadIdx.x][i]);
    }
}

// ---------------- conv1d (causal depthwise, K=4) + bias + silu ----------------
__global__ __launch_bounds__(256) void conv_kernel(const float* __restrict__ cw,
                                                   const float* __restrict__ cb) {
    int ch = blockIdx.x * 256 + threadIdx.x;
    int t  = blockIdx.y;
    int b  = t / LSEQ, l = t % LSEQ;
    float acc = cb[ch];
#pragma unroll
    for (int k = 0; k < KC; k++) {
        int lp = l - (KC - 1) + k;
        if (lp >= 0)
            acc = fmaf(g_zx[(size_t)(b * LSEQ + lp) * NPROJ + IF + ch], cw[k * XBCW + ch], acc);
    }
    acc = acc / (1.f + expf(-acc));
    g_xc[(size_t)t * XBCW + ch] = acc;
}

// ---------------- dt: softplus(dt_raw + bias), clip>=0 ----------------
__global__ __launch_bounds__(256) void dt_kernel(const float* __restrict__ dtb) {
    int idx = blockIdx.x * 256 + threadIdx.x;
    if (idx >= TTOT * HH) return;
    int t = idx / HH, h = idx % HH;
    float x = g_zx[(size_t)t * NPROJ + (NPROJ - HH) + h] + dtb[h];
    float sp = (x > 0.f) ? (x + log1pf(expf(-x))) : log1pf(expf(x));
    g_dt[idx] = fmaxf(sp, 0.f);
}

// ---------------- per-chunk inclusive cumsum of A*dt ----------------
__global__ __launch_bounds__(256) void acum_kernel(const float* __restrict__ alog) {
    int bx = blockIdx.x;
    int c  = bx % CN;
    int h  = (bx / CN) % HH;
    int b  = bx / (CN * HH);
    int s  = threadIdx.x;
    int t  = b * LSEQ + c * CSZ + s;
    float A = -expf(alog[h]);
    __shared__ float a[CSZ];
    a[s] = A * g_dt[(size_t)t * HH + h];
    __syncthreads();
    for (int off = 1; off < CSZ; off <<= 1) {
        float add = (s >= off) ? a[s - off] : 0.f;
        __syncthreads();
        a[s] += add;
        __syncthreads();
    }
    g_ac[(size_t)((b * HH + h) * CN + c) * CSZ + s] = a[s];
}

// ================= chunk state via TF32 mma =================
#define CS_AS 68
#define CS_BS 136

__global__ __launch_bounds__(256) void chunkstate_mma_kernel() {
    extern __shared__ float sm[];
    float* As = sm;
    float* Bs = sm + 64 * CS_AS;

    int bx = blockIdx.x;
    int h = bx % HH;
    int c = (bx / HH) % CN;
    int b = bx / (HH * CN);
    int tid = threadIdx.x, lane = tid & 31, warpId = tid >> 5;
    int gid = lane >> 2, tig = lane & 3;
    int warpM = warpId & 1, warpN = warpId >> 1;
    int acbase = ((b * HH + h) * CN + c) * CSZ;
    int tbase = b * LSEQ + c * CSZ;
    float Asum = g_ac[acbase + CSZ - 1];

    float acc[2][4][4];
#pragma unroll
    for (int mt = 0; mt < 2; mt++)
#pragma unroll
        for (int nt = 0; nt < 4; nt++)
#pragma unroll
            for (int e = 0; e < 4; e++) acc[mt][nt][e] = 0.f;

    for (int kt = 0; kt < 4; kt++) {
        for (int i = tid; i < 64 * 64; i += 256) {
            int l = i >> 6, p = i & 63;
            int ts = tbase + kt * 64 + l;
            float v = g_xc[(size_t)ts * XBCW + h * PP + p] * g_dt[(size_t)ts * HH + h];
            As[p * CS_AS + l] = f2tf32(v);
        }
        for (int i = tid; i < 64 * 128; i += 256) {
            int l = i >> 7, n = i & 127;
            int ts = tbase + kt * 64 + l;
            float dec = expf(Asum - g_ac[acbase + kt * 64 + l]);
            Bs[l * CS_BS + n] = f2tf32(g_xc[(size_t)ts * XBCW + IF + n] * dec);
        }
        __syncthreads();
#pragma unroll
        for (int k8 = 0; k8 < 8; k8++) {
            int k0 = k8 * 8;
            uint32_t af[2][4];
#pragma unroll
            for (int mt = 0; mt < 2; mt++) {
                int m = warpM * 32 + mt * 16;
                af[mt][0] = fu(As[(m + gid) * CS_AS + k0 + tig]);
                af[mt][1] = fu(As[(m + gid + 8) * CS_AS + k0 + tig]);
                af[mt][2] = fu(As[(m + gid) * CS_AS + k0 + tig + 4]);
                af[mt][3] = fu(As[(m + gid + 8) * CS_AS + k0 + tig + 4]);
            }
#pragma unroll
            for (int nt = 0; nt < 4; nt++) {
                int n = warpN * 32 + nt * 8 + gid;
                uint32_t b0 = fu(Bs[(k0 + tig) * CS_BS + n]);
                uint32_t b1 = fu(Bs[(k0 + tig + 4) * CS_BS + n]);
#pragma unroll
                for (int mt = 0; mt < 2; mt++)
                    mma_tf32(acc[mt][nt], af[mt][0], af[mt][1], af[mt][2], af[mt][3], b0, b1);
            }
        }
        __syncthreads();
    }

    size_t base = ((size_t)((b * CN + c) * HH + h)) * PP * NST;
#pragma unroll
    for (int mt = 0; mt < 2; mt++) {
        int p0 = warpM * 32 + mt * 16 + gid;
#pragma unroll
        for (int nt = 0; nt < 4; nt++) {
            int n0 = warpN * 32 + nt * 8 + tig * 2;
            g_ls[base + (size_t)p0 * NST + n0]           = acc[mt][nt][0];
            g_ls[base + (size_t)p0 * NST + n0 + 1]       = acc[mt][nt][1];
            g_ls[base + (size_t)(p0 + 8) * NST + n0]     = acc[mt][nt][2];
            g_ls[base + (size_t)(p0 + 8) * NST + n0 + 1] = acc[mt][nt][3];
        }
    }
}

// ---------------- inter-chunk recurrence over 16 chunks ----------------
__global__ __launch_bounds__(256) void recur_kernel() {
    int bh = blockIdx.x;
    int b = bh / HH, h = bh % HH;
    int tid = threadIdx.x;
    float st[32];
#pragma unroll
    for (int e = 0; e < 32; e++) st[e] = 0.f;
    for (int c = 0; c < CN; c++) {
        float es = expf(g_ac[(size_t)((b * HH + h) * CN + c) * CSZ + CSZ - 1]);
        size_t base = ((size_t)((b * CN + c) * HH + h)) * PP * NST;
#pragma unroll
        for (int e = 0; e < 32; e++) {
            int idx = tid + e * 256;
            g_ps[base + idx] = st[e];
            st[e] = fmaf(st[e], es, g_ls[base + idx]);
        }
    }
}

// ================= Y via TF32 mma =================
#define YD_CS 132
#define YD_XS 72
#define YD_GS 68

__global__ __launch_bounds__(256) void ydiag_mma_kernel(const float* __restrict__ Darr) {
    extern __shared__ float sm[];
    float* Cs  = sm;
    float* Bst = Cs + 64 * YD_CS;
    float* Xs  = Bst + 64 * YD_CS;
    float* Gs  = Xs + 64 * YD_XS;
    float* aL  = Gs + 64 * YD_GS;
    float* aS  = aL + 64;

    int lt  = blockIdx.x;
    int bch = blockIdx.y;
    int h = bch % HH;
    int c = (bch / HH) % CN;
    int b = bch / (HH * CN);
    int tid = threadIdx.x, lane = tid & 31, warpId = tid >> 5;
    int gid = lane >> 2, tig = lane & 3;
    int m0 = (warpId & 3) * 16;
    int n0 = (warpId >> 2) * 32;
    int acbase = ((b * HH + h) * CN + c) * CSZ;
    int tbase = b * LSEQ + c * CSZ;

    for (int i = tid; i < 64 * 128; i += 256) {
        int l = i >> 7, n = i & 127;
        Cs[l * YD_CS + n] = f2tf32(g_xc[(size_t)(tbase + lt * 64 + l) * XBCW + IF + NST + n]);
    }
    if (tid < 64) aL[tid] = g_ac[acbase + lt * 64 + tid];

    float accD[4][4];
#pragma unroll
    for (int nt = 0; nt < 4; nt++)
#pragma unroll
        for (int e = 0; e < 4; e++) accD[nt][e] = 0.f;

    for (int st = 0; st <= lt; st++) {
        __syncthreads();
        for (int i = tid; i < 64 * 128; i += 256) {
            int s = i >> 7, n = i & 127;
            Bst[s * YD_CS + n] = f2tf32(g_xc[(size_t)(tbase + st * 64 + s) * XBCW + IF + n]);
        }
        for (int i = tid; i < 64 * 64; i += 256) {
            int s = i >> 6, p = i & 63;
            int ts = tbase + st * 64 + s;
            Xs[s * YD_XS + p] = f2tf32(g_xc[(size_t)ts * XBCW + h * PP + p] * g_dt[(size_t)ts * HH + h]);
        }
        if (tid < 64) aS[tid] = g_ac[acbase + st * 64 + tid];
        __syncthreads();

        float g4[4][4];
#pragma unroll
        for (int nt = 0; nt < 4; nt++)
#pragma unroll
            for (int e = 0; e < 4; e++) g4[nt][e] = 0.f;
#pragma unroll
        for (int k8 = 0; k8 < 16; k8++) {
            int k0 = k8 * 8;
            uint32_t a0 = fu(Cs[(m0 + gid) * YD_CS + k0 + tig]);
            uint32_t a1 = fu(Cs[(m0 + gid + 8) * YD_CS + k0 + tig]);
            uint32_t a2 = fu(Cs[(m0 + gid) * YD_CS + k0 + tig + 4]);
            uint32_t a3 = fu(Cs[(m0 + gid + 8) * YD_CS + k0 + tig + 4]);
#pragma unroll
            for (int nt = 0; nt < 4; nt++) {
                int s = n0 + nt * 8 + gid;
                uint32_t b0 = fu(Bst[s * YD_CS + k0 + tig]);
                uint32_t b1 = fu(Bst[s * YD_CS + k0 + tig + 4]);
                mma_tf32(g4[nt], a0, a1, a2, a3, b0, b1);
            }
        }
        {
            int lA = m0 + gid, lB = lA + 8;
            int glA = lt * 64 + lA, glB = glA + 8;
            float aLA = aL[lA], aLB = aL[lB];
#pragma unroll
            for (int nt = 0; nt < 4; nt++) {
                int s0 = n0 + nt * 8 + tig * 2;
                int gs0 = st * 64 + s0;
                float as0 = aS[s0], as1 = aS[s0 + 1];
                float v0 = (gs0     <= glA) ? g4[nt][0] * expf(aLA - as0) : 0.f;
                float v1 = (gs0 + 1 <= glA) ? g4[nt][1] * expf(aLA - as1) : 0.f;
                float v2 = (gs0     <= glB) ? g4[nt][2] * expf(aLB - as0) : 0.f;
                float v3 = (gs0 + 1 <= glB) ? g4[nt][3] * expf(aLB - as1) : 0.f;
                Gs[lA * YD_GS + s0]     = f2tf32(v0);
                Gs[lA * YD_GS + s0 + 1] = f2tf32(v1);
                Gs[lB * YD_GS + s0]     = f2tf32(v2);
                Gs[lB * YD_GS + s0 + 1] = f2tf32(v3);
            }
        }
        __syncthreads();
#pragma unroll
        for (int k8 = 0; k8 < 8; k8++) {
            int k0 = k8 * 8;
            uint32_t a0 = fu(Gs[(m0 + gid) * YD_GS + k0 + tig]);
            uint32_t a1 = fu(Gs[(m0 + gid + 8) * YD_GS + k0 + tig]);
            uint32_t a2 = fu(Gs[(m0 + gid) * YD_GS + k0 + tig + 4]);
            uint32_t a3 = fu(Gs[(m0 + gid + 8) * YD_GS + k0 + tig + 4]);
#pragma unroll
            for (int nt = 0; nt < 4; nt++) {
                int p = n0 + nt * 8 + gid;
                uint32_t b0 = fu(Xs[(k0 + tig) * YD_XS + p]);
                uint32_t b1 = fu(Xs[(k0 + tig + 4) * YD_XS + p]);
                mma_tf32(accD[nt], a0, a1, a2, a3, b0, b1);
            }
        }
    }

    __syncthreads();
    {
        size_t sbase = ((size_t)((b * CN + c) * HH + h)) * PP * NST;
        for (int i = tid; i < 64 * 128; i += 256) {
            int p = i >> 7, n = i & 127;
            Bst[p * YD_CS + n] = f2tf32(g_ps[sbase + (size_t)p * NST + n]);
        }
    }
    __syncthreads();
    float off4[4][4];
#pragma unroll
    for (int nt = 0; nt < 4; nt++)
#pragma unroll
        for (int e = 0; e < 4; e++) off4[nt][e] = 0.f;
#pragma unroll
    for (int k8 = 0; k8 < 16; k8++) {
        int k0 = k8 * 8;
        uint32_t a0 = fu(Cs[(m0 + gid) * YD_CS + k0 + tig]);
        uint32_t a1 = fu(Cs[(m0 + gid + 8) * YD_CS + k0 + tig]);
        uint32_t a2 = fu(Cs[(m0 + gid) * YD_CS + k0 + tig + 4]);
        uint32_t a3 = fu(Cs[(m0 + gid + 8) * YD_CS + k0 + tig + 4]);
#pragma unroll
        for (int nt = 0; nt < 4; nt++) {
            int p = n0 + nt * 8 + gid;
            uint32_t b0 = fu(Bst[p * YD_CS + k0 + tig]);
            uint32_t b1 = fu(Bst[p * YD_CS + k0 + tig + 4]);
            mma_tf32(off4[nt], a0, a1, a2, a3, b0, b1);
        }
    }

    {
        int lA = m0 + gid, lB = lA + 8;
        float e0 = expf(aL[lA]), e1 = expf(aL[lB]);
        float Dh = Darr[h];
        int tA = tbase + lt * 64 + lA;
        int tB = tbase + lt * 64 + lB;
#pragma unroll
        for (int nt = 0; nt < 4; nt++) {
            int p0 = n0 + nt * 8 + tig * 2;
            float xA0 = g_xc[(size_t)tA * XBCW + h * PP + p0];
            float xA1 = g_xc[(size_t)tA * XBCW + h * PP + p0 + 1];
            float xB0 = g_xc[(size_t)tB * XBCW + h * PP + p0];
            float xB1 = g_xc[(size_t)tB * XBCW + h * PP + p0 + 1];
            g_y[(size_t)tA * IF + h * PP + p0]     = accD[nt][0] + e0 * off4[nt][0] + Dh * xA0;
            g_y[(size_t)tA * IF + h * PP + p0 + 1] = accD[nt][1] + e0 * off4[nt][1] + Dh * xA1;
            g_y[(size_t)tB * IF + h * PP + p0]     = accD[nt][2] + e1 * off4[nt][2] + Dh * xB0;
            g_y[(size_t)tB * IF + h * PP + p0 + 1] = accD[nt][3] + e1 * off4[nt][3] + Dh * xB1;
        }
    }
}

// ---------------- gated RMSNorm (in-place, stores tf32-rounded) ----------------
__global__ __launch_bounds__(256) void gnorm_kernel(const float* __restrict__ nw) {
    int t = blockIdx.x;
    int tid = threadIdx.x;
    float vals[6];
    float ss = 0.f;
#pragma unroll
    for (int k = 0; k < 6; k++) {
        int i = tid + k * 256;
        float y = g_y[(size_t)t * IF + i];
        float z = g_zx[(size_t)t * NPROJ + i];
        float xf = y * (z / (1.f + expf(-z)));
        vals[k] = xf;
        ss += xf * xf;
    }
    __shared__ float red[256];
    __shared__ float s_scale;
    red[tid] = ss;
    __syncthreads();
    for (int o = 128; o > 0; o >>= 1) {
        if (tid < o) red[tid] += red[tid + o];
        __syncthreads();
    }
    if (tid == 0) s_scale = rsqrtf(red[0] / (float)IF + 1e-5f);
    __syncthreads();
    float sc = s_scale;
#pragma unroll
    for (int k = 0; k < 6; k++) {
        int i = tid + k * 256;
        g_y[(size_t)t * IF + i] = f2tf32(vals[k] * sc * nw[i]);
    }
}

// ---------------- host launcher ----------------
extern "C" void kernel_launch(void* const* d_in, const int* in_sizes, int n_in,
                              void* d_out, int out_size) {
    const float* hs   = (const float*)d_in[0];
    const float* inw  = (const float*)d_in[1];
    const float* cw   = (const float*)d_in[2];
    const float* cb   = (const float*)d_in[3];
    const float* dtb  = (const float*)d_in[4];
    const float* alog = (const float*)d_in[5];
    const float* Dp   = (const float*)d_in[6];
    const float* nw   = (const float*)d_in[7];
    const float* ow   = (const float*)d_in[8];
    float* out = (float*)d_out;

    void *p_zx = nullptr, *p_y = nullptr, *p_hsr = nullptr, *p_inwT = nullptr, *p_owT = nullptr;
    cudaGetSymbolAddress(&p_zx, g_zx);
    cudaGetSymbolAddress(&p_y, g_y);
    cudaGetSymbolAddress(&p_hsr, g_hsr);
    cudaGetSymbolAddress(&p_inwT, g_inwT);
    cudaGetSymbolAddress(&p_owT, g_owT);

    int smem_gemm = 3 * 2 * STAGE_F * 4;   // 61440
    int smem_cs = (64 * CS_AS + 64 * CS_BS) * 4;
    int smem_y  = (64 * YD_CS * 2 + 64 * YD_XS + 64 * YD_GS + 128) * 4;
    cudaFuncSetAttribute(tf32gemm_ldsm_kernel, cudaFuncAttributeMaxDynamicSharedMemorySize, smem_gemm);
    cudaFuncSetAttribute(chunkstate_mma_kernel, cudaFuncAttributeMaxDynamicSharedMemorySize, smem_cs);
    cudaFuncSetAttribute(ydiag_mma_kernel, cudaFuncAttributeMaxDynamicSharedMemorySize, smem_y);

    // 0. prep: round hs; transpose+round weights
    round_kernel<<<(TTOT * HIDD + 255) / 256, 256>>>(hs, (float*)p_hsr, TTOT * HIDD);
    {
        dim3 g((NPROJ + 31) / 32, (HIDD + 31) / 32);
        transpose_round_kernel<<<g, dim3(32, 8)>>>(inw, (float*)p_inwT, HIDD, NPROJ);
    }
    {
        dim3 g((HIDD + 31) / 32, (IF + 31) / 32);
        transpose_round_kernel<<<g, dim3(32, 8)>>>(ow, (float*)p_owT, IF, HIDD);
    }

    // 1. in_proj GEMM: (8192 x 768) @ (768 x 3352)
    {
        dim3 grid((NPROJ + 127) / 128, TTOT / 128);
        tf32gemm_ldsm_kernel<<<grid, 256, smem_gemm>>>((const float*)p_hsr, (const float*)p_inwT,
                                                       (float*)p_zx, TTOT, NPROJ, HIDD);
    }
    // 2. conv + silu
    {
        dim3 grid(XBCW / 256, TTOT);
        conv_kernel<<<grid, 256>>>(cw, cb);
    }
    // 3. dt softplus
    dt_kernel<<<(TTOT * HH + 255) / 256, 256>>>(dtb);
    // 4. per-chunk cumsum of A*dt
    acum_kernel<<<BSZ * HH * CN, 256>>>(alog);
    // 5. local chunk states (tf32 mma)
    chunkstate_mma_kernel<<<BSZ * CN * HH, 256, smem_cs>>>();
    // 6. inter-chunk recurrence
    recur_kernel<<<BSZ * HH, 256>>>();
    // 7. Y_diag + Y_off + D residual (tf32 mma)
    {
        dim3 grid(4, BSZ * CN * HH);
        ydiag_mma_kernel<<<grid, 256, smem_y>>>(Dp);
    }
    // 8. gated RMSNorm (writes tf32-rounded)
    gnorm_kernel<<<TTOT, 256>>>(nw);
    // 9. out_proj GEMM: (8192 x 1536) @ (1536 x 768) -> d_out
    {
        dim3 grid(HIDD / 128, TTOT / 128);
        tf32gemm_ldsm_kernel<<<grid, 256, smem_gemm>>>((const float*)p_y, (const float*)p_owT,
                                                       out, TTOT, HIDD, IF);
    }
}

// round 5
// speedup vs baseline: 2.6555x; 1.0393x over previous
#include <cuda_runtime.h>
#include <cuda_bf16.h>
#include <math.h>
#include <stdint.h>

// ---------------- problem constants ----------------
#define BSZ   2
#define LSEQ  4096
#define TTOT  8192          // BSZ*LSEQ
#define HIDD  768
#define IF    1536          // I
#define NST   128           // N
#define HH    24            // H
#define PP    64            // P
#define CSZ   256           // chunk size
#define CN    16            // LSEQ/CSZ
#define KC    4             // conv kernel
#define NPROJ 3352          // 2*(I+N)+H
#define XBCW  1792          // I+2N

// ---------------- scratch (static device globals; no allocs) ----------------
__device__ float g_zx[TTOT * NPROJ];               // in_proj output (z | xBC | dt)
__device__ float g_xc[TTOT * XBCW];                // conv+silu output
__device__ float g_dt[TTOT * HH];                  // softplus(dt+bias)
__device__ float g_ac[BSZ * HH * CN * CSZ];        // per-chunk inclusive cumsum of A*dt
__device__ float g_ls[BSZ * CN * HH * PP * NST];   // local chunk states
__device__ float g_ps[BSZ * CN * HH * PP * NST];   // prefix states entering chunk
__device__ float g_y [TTOT * IF];                  // y (tf32-rounded after gnorm)
__device__ float g_hsr [TTOT * HIDD];              // hs rounded to tf32
__device__ float g_inwT[NPROJ * HIDD];             // in_proj_w^T, tf32
__device__ float g_owT [HIDD * IF];                // out_proj_w^T, tf32

// ---------------- helpers ----------------
__device__ __forceinline__ float f2tf32(float x) {
    uint32_t r;
    asm("cvt.rna.tf32.f32 %0, %1;" : "=r"(r) : "f"(x));
    return __uint_as_float(r);
}
__device__ __forceinline__ uint32_t fu(float x) { return __float_as_uint(x); }

__device__ __forceinline__ void mma_tf32(float* c, uint32_t a0, uint32_t a1,
                                         uint32_t a2, uint32_t a3,
                                         uint32_t b0, uint32_t b1) {
    asm volatile(
        "mma.sync.aligned.m16n8k8.row.col.f32.tf32.tf32.f32 "
        "{%0,%1,%2,%3}, {%4,%5,%6,%7}, {%8,%9}, {%0,%1,%2,%3};\n"
        : "+f"(c[0]), "+f"(c[1]), "+f"(c[2]), "+f"(c[3])
        : "r"(a0), "r"(a1), "r"(a2), "r"(a3), "r"(b0), "r"(b1));
}
__device__ __forceinline__ void ldsm_x4(uint32_t addr, uint32_t& r0, uint32_t& r1,
                                        uint32_t& r2, uint32_t& r3) {
    asm volatile("ldmatrix.sync.aligned.m8n8.x4.shared.b16 {%0,%1,%2,%3}, [%4];"
                 : "=r"(r0), "=r"(r1), "=r"(r2), "=r"(r3) : "r"(addr));
}
__device__ __forceinline__ void cpasync16(uint32_t daddr, const void* gaddr, bool pred) {
    int sz = pred ? 16 : 0;
    asm volatile("cp.async.cg.shared.global [%0], [%1], 16, %2;"
                 :: "r"(daddr), "l"(gaddr), "r"(sz));
}
#define CP_COMMIT()  asm volatile("cp.async.commit_group;")
#define CP_WAIT1()   asm volatile("cp.async.wait_group 1;")

// ================= TF32 GEMM: ldmatrix + cp.async, BK=32, 3 stages =================
// C = A(MxK) @ Bt^T where Bt is [N][K] row-major, both pre-rounded tf32.
// BM=BN=128, BK=32, 256 thr = 8 warps (warpM 2 x warpN 4), warp tile 64x32.
#define GST 36               // row stride (floats): 32 + 4 pad, conflict-free ldmatrix
#define STAGE_F (128 * GST)  // floats per matrix per stage

__global__ __launch_bounds__(256, 2) void tf32gemm_ldsm_kernel(const float* __restrict__ A,
                                                               const float* __restrict__ Bt,
                                                               float* __restrict__ C,
                                                               int M, int N, int K) {
    extern __shared__ float sm[];
    const int tid = threadIdx.x;
    const int lane = tid & 31;
    const int warpId = tid >> 5;
    const int gid = lane >> 2, tig = lane & 3;
    const int warpM = warpId & 1;
    const int warpN = warpId >> 1;
    const int rowBase = blockIdx.y * 128;
    const int colBase = blockIdx.x * 128;
    const int nk = K >> 5;

    uint32_t smBase = (uint32_t)__cvta_generic_to_shared(sm);

    // cp.async per-thread: row = tid>>1, 4 consecutive 16B chunks at (tid&1)*4
    const int cpr = tid >> 1;
    const int cpc = (tid & 1) * 4;
    const int nB = colBase + cpr;
    const bool bOK = nB < N;
    const int nBc = bOK ? nB : 0;
    const uint32_t cpOff = (uint32_t)(cpr * GST + cpc * 4) * 4;

    auto issue = [&](int kt, int stage) {
        int k0 = kt << 5;
        uint32_t sA = smBase + (uint32_t)(stage * 2 * STAGE_F) * 4 + cpOff;
        uint32_t sB = smBase + (uint32_t)((stage * 2 + 1) * STAGE_F) * 4 + cpOff;
        const float* ga = &A[(size_t)(rowBase + cpr) * K + k0 + cpc * 4];
        const float* gb = &Bt[(size_t)nBc * K + k0 + cpc * 4];
#pragma unroll
        for (int i = 0; i < 4; i++) {
            cpasync16(sA + i * 16, ga + i * 4, true);
            cpasync16(sB + i * 16, gb + i * 4, bOK);
        }
        CP_COMMIT();
    };

    // ldmatrix per-lane offsets (floats within tile)
    const uint32_t aLaneOff = (uint32_t)((lane & 15) * GST + (lane >> 4) * 4);
    const uint32_t bLaneOff = (uint32_t)(((lane >> 4) * 8 + (lane & 7)) * GST + ((lane >> 3) & 1) * 4);

    float acc[4][4][4];
#pragma unroll
    for (int mt = 0; mt < 4; mt++)
#pragma unroll
        for (int nt = 0; nt < 4; nt++)
#pragma unroll
            for (int e = 0; e < 4; e++) acc[mt][nt][e] = 0.f;

    issue(0, 0);
    if (nk > 1) issue(1, 1);

    for (int kt = 0; kt < nk; kt++) {
        CP_WAIT1();
        __syncthreads();
        if (kt + 2 < nk) issue(kt + 2, (kt + 2) % 3);

        int stage = kt % 3;
        uint32_t aBase = smBase + (uint32_t)(stage * 2 * STAGE_F) * 4;
        uint32_t bBase = smBase + (uint32_t)((stage * 2 + 1) * STAGE_F) * 4;

#pragma unroll
        for (int ks = 0; ks < 4; ks++) {
            uint32_t bfr[4][2];
#pragma unroll
            for (int pair = 0; pair < 2; pair++) {
                uint32_t addr = bBase + ((uint32_t)((warpN * 32 + pair * 16) * GST + ks * 8) + bLaneOff) * 4;
                uint32_t r0, r1, r2, r3;
                ldsm_x4(addr, r0, r1, r2, r3);
                bfr[pair * 2][0] = r0; bfr[pair * 2][1] = r1;
                bfr[pair * 2 + 1][0] = r2; bfr[pair * 2 + 1][1] = r3;
            }
#pragma unroll
            for (int mt = 0; mt < 4; mt++) {
                uint32_t addr = aBase + ((uint32_t)((warpM * 64 + mt * 16) * GST + ks * 8) + aLaneOff) * 4;
                uint32_t a0, a1, a2, a3;
                ldsm_x4(addr, a0, a1, a2, a3);
#pragma unroll
                for (int nt = 0; nt < 4; nt++)
                    mma_tf32(acc[mt][nt], a0, a1, a2, a3, bfr[nt][0], bfr[nt][1]);
            }
        }
    }

    // epilogue
#pragma unroll
    for (int mt = 0; mt < 4; mt++) {
        int r0 = rowBase + warpM * 64 + mt * 16 + gid;
#pragma unroll
        for (int nt = 0; nt < 4; nt++) {
            int c0 = colBase + warpN * 32 + nt * 8 + tig * 2;
            if (c0 < N)     C[(size_t)r0 * N + c0]           = acc[mt][nt][0];
            if (c0 + 1 < N) C[(size_t)r0 * N + c0 + 1]       = acc[mt][nt][1];
            if (c0 < N)     C[(size_t)(r0 + 8) * N + c0]     = acc[mt][nt][2];
            if (c0 + 1 < N) C[(size_t)(r0 + 8) * N + c0 + 1] = acc[mt][nt][3];
        }
    }
}

// ---------------- prep: round / transpose+round ----------------
__global__ __launch_bounds__(256) void round_kernel(const float* __restrict__ src,
                                                    float* __restrict__ dst, int n) {
    int i = blockIdx.x * 256 + threadIdx.x;
    if (i < n) dst[i] = f2tf32(src[i]);
}

__global__ void transpose_round_kernel(const float* __restrict__ src,
                                       float* __restrict__ dst, int R, int Cc) {
    __shared__ float t[32][33];
    int c0 = blockIdx.x * 32, r0 = blockIdx.y * 32;
    int x = c0 + threadIdx.x;
    for (int i = threadIdx.y; i < 32; i += 8) {
        int y = r0 + i;
        if (x < Cc && y < R) t[i][threadIdx.x] = src[(size_t)y * Cc + x];
    }
    __syncthreads();
    int xo = r0 + threadIdx.x;
    for (int i = threadIdx.y; i < 32; i += 8) {
        int yo = c0 + i;
        if (xo < R && yo < Cc) dst[(size_t)yo * R + xo] = f2tf32(t[threadIdx.x][i]);
    }
}

// ---------------- conv1d (causal depthwise, K=4) + bias + silu, float4 ----------------
__global__ __launch_bounds__(224) void conv_kernel(const float* __restrict__ cw,
                                                   const float* __restrict__ cb) {
    int c4 = blockIdx.x * 224 + threadIdx.x;   // 0..447
    int ch = c4 * 4;
    int t  = blockIdx.y;
    int b  = t / LSEQ, l = t % LSEQ;
    float4 acc = *reinterpret_cast<const float4*>(&cb[ch]);
#pragma unroll
    for (int k = 0; k < KC; k++) {
        int lp = l - (KC - 1) + k;
        if (lp >= 0) {
            float4 xv = *reinterpret_cast<const float4*>(&g_zx[(size_t)(b * LSEQ + lp) * NPROJ + IF + ch]);
            float4 wv = *reinterpret_cast<const float4*>(&cw[k * XBCW + ch]);
            acc.x = fmaf(xv.x, wv.x, acc.x);
            acc.y = fmaf(xv.y, wv.y, acc.y);
            acc.z = fmaf(xv.z, wv.z, acc.z);
            acc.w = fmaf(xv.w, wv.w, acc.w);
        }
    }
    acc.x = acc.x / (1.f + expf(-acc.x));
    acc.y = acc.y / (1.f + expf(-acc.y));
    acc.z = acc.z / (1.f + expf(-acc.z));
    acc.w = acc.w / (1.f + expf(-acc.w));
    *reinterpret_cast<float4*>(&g_xc[(size_t)t * XBCW + ch]) = acc;
}

// ---------------- dt: softplus(dt_raw + bias), clip>=0 ----------------
__global__ __launch_bounds__(256) void dt_kernel(const float* __restrict__ dtb) {
    int idx = blockIdx.x * 256 + threadIdx.x;
    if (idx >= TTOT * HH) return;
    int t = idx / HH, h = idx % HH;
    float x = g_zx[(size_t)t * NPROJ + (NPROJ - HH) + h] + dtb[h];
    float sp = (x > 0.f) ? (x + log1pf(expf(-x))) : log1pf(expf(x));
    g_dt[idx] = fmaxf(sp, 0.f);
}

// ---------------- per-chunk inclusive cumsum of A*dt ----------------
__global__ __launch_bounds__(256) void acum_kernel(const float* __restrict__ alog) {
    int bx = blockIdx.x;
    int c  = bx % CN;
    int h  = (bx / CN) % HH;
    int b  = bx / (CN * HH);
    int s  = threadIdx.x;
    int t  = b * LSEQ + c * CSZ + s;
    float A = -expf(alog[h]);
    __shared__ float a[CSZ];
    a[s] = A * g_dt[(size_t)t * HH + h];
    __syncthreads();
    for (int off = 1; off < CSZ; off <<= 1) {
        float add = (s >= off) ? a[s - off] : 0.f;
        __syncthreads();
        a[s] += add;
        __syncthreads();
    }
    g_ac[(size_t)((b * HH + h) * CN + c) * CSZ + s] = a[s];
}

// ================= chunk state via TF32 mma =================
#define CS_AS 68
#define CS_BS 136

__global__ __launch_bounds__(256) void chunkstate_mma_kernel() {
    extern __shared__ float sm[];
    float* As = sm;
    float* Bs = sm + 64 * CS_AS;

    int bx = blockIdx.x;
    int h = bx % HH;
    int c = (bx / HH) % CN;
    int b = bx / (HH * CN);
    int tid = threadIdx.x, lane = tid & 31, warpId = tid >> 5;
    int gid = lane >> 2, tig = lane & 3;
    int warpM = warpId & 1, warpN = warpId >> 1;
    int acbase = ((b * HH + h) * CN + c) * CSZ;
    int tbase = b * LSEQ + c * CSZ;
    float Asum = g_ac[acbase + CSZ - 1];

    float acc[2][4][4];
#pragma unroll
    for (int mt = 0; mt < 2; mt++)
#pragma unroll
        for (int nt = 0; nt < 4; nt++)
#pragma unroll
            for (int e = 0; e < 4; e++) acc[mt][nt][e] = 0.f;

    for (int kt = 0; kt < 4; kt++) {
        for (int i = tid; i < 64 * 64; i += 256) {
            int l = i >> 6, p = i & 63;
            int ts = tbase + kt * 64 + l;
            float v = g_xc[(size_t)ts * XBCW + h * PP + p] * g_dt[(size_t)ts * HH + h];
            As[p * CS_AS + l] = f2tf32(v);
        }
        for (int i = tid; i < 64 * 128; i += 256) {
            int l = i >> 7, n = i & 127;
            int ts = tbase + kt * 64 + l;
            float dec = expf(Asum - g_ac[acbase + kt * 64 + l]);
            Bs[l * CS_BS + n] = f2tf32(g_xc[(size_t)ts * XBCW + IF + n] * dec);
        }
        __syncthreads();
#pragma unroll
        for (int k8 = 0; k8 < 8; k8++) {
            int k0 = k8 * 8;
            uint32_t af[2][4];
#pragma unroll
            for (int mt = 0; mt < 2; mt++) {
                int m = warpM * 32 + mt * 16;
                af[mt][0] = fu(As[(m + gid) * CS_AS + k0 + tig]);
                af[mt][1] = fu(As[(m + gid + 8) * CS_AS + k0 + tig]);
                af[mt][2] = fu(As[(m + gid) * CS_AS + k0 + tig + 4]);
                af[mt][3] = fu(As[(m + gid + 8) * CS_AS + k0 + tig + 4]);
            }
#pragma unroll
            for (int nt = 0; nt < 4; nt++) {
                int n = warpN * 32 + nt * 8 + gid;
                uint32_t b0 = fu(Bs[(k0 + tig) * CS_BS + n]);
                uint32_t b1 = fu(Bs[(k0 + tig + 4) * CS_BS + n]);
#pragma unroll
                for (int mt = 0; mt < 2; mt++)
                    mma_tf32(acc[mt][nt], af[mt][0], af[mt][1], af[mt][2], af[mt][3], b0, b1);
            }
        }
        __syncthreads();
    }

    size_t base = ((size_t)((b * CN + c) * HH + h)) * PP * NST;
#pragma unroll
    for (int mt = 0; mt < 2; mt++) {
        int p0 = warpM * 32 + mt * 16 + gid;
#pragma unroll
        for (int nt = 0; nt < 4; nt++) {
            int n0 = warpN * 32 + nt * 8 + tig * 2;
            g_ls[base + (size_t)p0 * NST + n0]           = acc[mt][nt][0];
            g_ls[base + (size_t)p0 * NST + n0 + 1]       = acc[mt][nt][1];
            g_ls[base + (size_t)(p0 + 8) * NST + n0]     = acc[mt][nt][2];
            g_ls[base + (size_t)(p0 + 8) * NST + n0 + 1] = acc[mt][nt][3];
        }
    }
}

// ---------------- inter-chunk recurrence (1 element/thread) ----------------
__global__ __launch_bounds__(256) void recur_kernel() {
    int blk = blockIdx.x;            // BSZ*HH*32
    int seg = blk & 31;
    int bh  = blk >> 5;
    int b = bh / HH, h = bh % HH;
    int idx = seg * 256 + threadIdx.x;   // 0..8191
    float st = 0.f;
#pragma unroll
    for (int c = 0; c < CN; c++) {
        float es = expf(g_ac[(size_t)((b * HH + h) * CN + c) * CSZ + CSZ - 1]);
        size_t base = ((size_t)((b * CN + c) * HH + h)) * PP * NST;
        g_ps[base + idx] = st;
        st = fmaf(st, es, g_ls[base + idx]);
    }
}

// ================= Y via TF32 mma =================
#define YD_CS 132
#define YD_XS 72
#define YD_GS 68

__global__ __launch_bounds__(256) void ydiag_mma_kernel(const float* __restrict__ Darr) {
    extern __shared__ float sm[];
    float* Cs  = sm;
    float* Bst = Cs + 64 * YD_CS;
    float* Xs  = Bst + 64 * YD_CS;
    float* Gs  = Xs + 64 * YD_XS;
    float* aL  = Gs + 64 * YD_GS;
    float* aS  = aL + 64;

    int lt  = blockIdx.x;
    int bch = blockIdx.y;
    int h = bch % HH;
    int c = (bch / HH) % CN;
    int b = bch / (HH * CN);
    int tid = threadIdx.x, lane = tid & 31, warpId = tid >> 5;
    int gid = lane >> 2, tig = lane & 3;
    int m0 = (warpId & 3) * 16;
    int n0 = (warpId >> 2) * 32;
    int acbase = ((b * HH + h) * CN + c) * CSZ;
    int tbase = b * LSEQ + c * CSZ;

    for (int i = tid; i < 64 * 128; i += 256) {
        int l = i >> 7, n = i & 127;
        Cs[l * YD_CS + n] = f2tf32(g_xc[(size_t)(tbase + lt * 64 + l) * XBCW + IF + NST + n]);
    }
    if (tid < 64) aL[tid] = g_ac[acbase + lt * 64 + tid];

    float accD[4][4];
#pragma unroll
    for (int nt = 0; nt < 4; nt++)
#pragma unroll
        for (int e = 0; e < 4; e++) accD[nt][e] = 0.f;

    for (int st = 0; st <= lt; st++) {
        __syncthreads();
        for (int i = tid; i < 64 * 128; i += 256) {
            int s = i >> 7, n = i & 127;
            Bst[s * YD_CS + n] = f2tf32(g_xc[(size_t)(tbase + st * 64 + s) * XBCW + IF + n]);
        }
        for (int i = tid; i < 64 * 64; i += 256) {
            int s = i >> 6, p = i & 63;
            int ts = tbase + st * 64 + s;
            Xs[s * YD_XS + p] = f2tf32(g_xc[(size_t)ts * XBCW + h * PP + p] * g_dt[(size_t)ts * HH + h]);
        }
        if (tid < 64) aS[tid] = g_ac[acbase + st * 64 + tid];
        __syncthreads();

        float g4[4][4];
#pragma unroll
        for (int nt = 0; nt < 4; nt++)
#pragma unroll
            for (int e = 0; e < 4; e++) g4[nt][e] = 0.f;
#pragma unroll
        for (int k8 = 0; k8 < 16; k8++) {
            int k0 = k8 * 8;
            uint32_t a0 = fu(Cs[(m0 + gid) * YD_CS + k0 + tig]);
            uint32_t a1 = fu(Cs[(m0 + gid + 8) * YD_CS + k0 + tig]);
            uint32_t a2 = fu(Cs[(m0 + gid) * YD_CS + k0 + tig + 4]);
            uint32_t a3 = fu(Cs[(m0 + gid + 8) * YD_CS + k0 + tig + 4]);
#pragma unroll
            for (int nt = 0; nt < 4; nt++) {
                int s = n0 + nt * 8 + gid;
                uint32_t b0 = fu(Bst[s * YD_CS + k0 + tig]);
                uint32_t b1 = fu(Bst[s * YD_CS + k0 + tig + 4]);
                mma_tf32(g4[nt], a0, a1, a2, a3, b0, b1);
            }
        }
        {
            int lA = m0 + gid, lB = lA + 8;
            int glA = lt * 64 + lA, glB = glA + 8;
            float aLA = aL[lA], aLB = aL[lB];
#pragma unroll
            for (int nt = 0; nt < 4; nt++) {
                int s0 = n0 + nt * 8 + tig * 2;
                int gs0 = st * 64 + s0;
                float as0 = aS[s0], as1 = aS[s0 + 1];
                float v0 = (gs0     <= glA) ? g4[nt][0] * expf(aLA - as0) : 0.f;
                float v1 = (gs0 + 1 <= glA) ? g4[nt][1] * expf(aLA - as1) : 0.f;
                float v2 = (gs0     <= glB) ? g4[nt][2] * expf(aLB - as0) : 0.f;
                float v3 = (gs0 + 1 <= glB) ? g4[nt][3] * expf(aLB - as1) : 0.f;
                Gs[lA * YD_GS + s0]     = f2tf32(v0);
                Gs[lA * YD_GS + s0 + 1] = f2tf32(v1);
                Gs[lB * YD_GS + s0]     = f2tf32(v2);
                Gs[lB * YD_GS + s0 + 1] = f2tf32(v3);
            }
        }
        __syncthreads();
#pragma unroll
        for (int k8 = 0; k8 < 8; k8++) {
            int k0 = k8 * 8;
            uint32_t a0 = fu(Gs[(m0 + gid) * YD_GS + k0 + tig]);
            uint32_t a1 = fu(Gs[(m0 + gid + 8) * YD_GS + k0 + tig]);
            uint32_t a2 = fu(Gs[(m0 + gid) * YD_GS + k0 + tig + 4]);
            uint32_t a3 = fu(Gs[(m0 + gid + 8) * YD_GS + k0 + tig + 4]);
#pragma unroll
            for (int nt = 0; nt < 4; nt++) {
                int p = n0 + nt * 8 + gid;
                uint32_t b0 = fu(Xs[(k0 + tig) * YD_XS + p]);
                uint32_t b1 = fu(Xs[(k0 + tig + 4) * YD_XS + p]);
                mma_tf32(accD[nt], a0, a1, a2, a3, b0, b1);
            }
        }
    }

    __syncthreads();
    {
        size_t sbase = ((size_t)((b * CN + c) * HH + h)) * PP * NST;
        for (int i = tid; i < 64 * 128; i += 256) {
            int p = i >> 7, n = i & 127;
            Bst[p * YD_CS + n] = f2tf32(g_ps[sbase + (size_t)p * NST + n]);
        }
    }
    __syncthreads();
    float off4[4][4];
#pragma unroll
    for (int nt = 0; nt < 4; nt++)
#pragma unroll
        for (int e = 0; e < 4; e++) off4[nt][e] = 0.f;
#pragma unroll
    for (int k8 = 0; k8 < 16; k8++) {
        int k0 = k8 * 8;
        uint32_t a0 = fu(Cs[(m0 + gid) * YD_CS + k0 + tig]);
        uint32_t a1 = fu(Cs[(m0 + gid + 8) * YD_CS + k0 + tig]);
        uint32_t a2 = fu(Cs[(m0 + gid) * YD_CS + k0 + tig + 4]);
        uint32_t a3 = fu(Cs[(m0 + gid + 8) * YD_CS + k0 + tig + 4]);
#pragma unroll
        for (int nt = 0; nt < 4; nt++) {
            int p = n0 + nt * 8 + gid;
            uint32_t b0 = fu(Bst[p * YD_CS + k0 + tig]);
            uint32_t b1 = fu(Bst[p * YD_CS + k0 + tig + 4]);
            mma_tf32(off4[nt], a0, a1, a2, a3, b0, b1);
        }
    }

    {
        int lA = m0 + gid, lB = lA + 8;
        float e0 = expf(aL[lA]), e1 = expf(aL[lB]);
        float Dh = Darr[h];
        int tA = tbase + lt * 64 + lA;
        int tB = tbase + lt * 64 + lB;
#pragma unroll
        for (int nt = 0; nt < 4; nt++) {
            int p0 = n0 + nt * 8 + tig * 2;
            float xA0 = g_xc[(size_t)tA * XBCW + h * PP + p0];
            float xA1 = g_xc[(size_t)tA * XBCW + h * PP + p0 + 1];
            float xB0 = g_xc[(size_t)tB * XBCW + h * PP + p0];
            float xB1 = g_xc[(size_t)tB * XBCW + h * PP + p0 + 1];
            g_y[(size_t)tA * IF + h * PP + p0]     = accD[nt][0] + e0 * off4[nt][0] + Dh * xA0;
            g_y[(size_t)tA * IF + h * PP + p0 + 1] = accD[nt][1] + e0 * off4[nt][1] + Dh * xA1;
            g_y[(size_t)tB * IF + h * PP + p0]     = accD[nt][2] + e1 * off4[nt][2] + Dh * xB0;
            g_y[(size_t)tB * IF + h * PP + p0 + 1] = accD[nt][3] + e1 * off4[nt][3] + Dh * xB1;
        }
    }
}

// ---------------- gated RMSNorm (float4, stores tf32-rounded) ----------------
__global__ __launch_bounds__(128) void gnorm_kernel(const float* __restrict__ nw) {
    int t = blockIdx.x;
    int tid = threadIdx.x;
    float4 v[3];
    float ss = 0.f;
#pragma unroll
    for (int k = 0; k < 3; k++) {
        int i = (tid + k * 128) * 4;
        float4 y = *reinterpret_cast<const float4*>(&g_y[(size_t)t * IF + i]);
        float4 z = *reinterpret_cast<const float4*>(&g_zx[(size_t)t * NPROJ + i]);
        float x0 = y.x * (z.x / (1.f + expf(-z.x)));
        float x1 = y.y * (z.y / (1.f + expf(-z.y)));
        float x2 = y.z * (z.z / (1.f + expf(-z.z)));
        float x3 = y.w * (z.w / (1.f + expf(-z.w)));
        v[k] = make_float4(x0, x1, x2, x3);
        ss += x0 * x0 + x1 * x1 + x2 * x2 + x3 * x3;
    }
    __shared__ float red[128];
    __shared__ float s_scale;
    red[tid] = ss;
    __syncthreads();
    for (int o = 64; o > 0; o >>= 1) {
        if (tid < o) red[tid] += red[tid + o];
        __syncthreads();
    }
    if (tid == 0) s_scale = rsqrtf(red[0] / (float)IF + 1e-5f);
    __syncthreads();
    float sc = s_scale;
#pragma unroll
    for (int k = 0; k < 3; k++) {
        int i = (tid + k * 128) * 4;
        float4 w = *reinterpret_cast<const float4*>(&nw[i]);
        float4 o;
        o.x = f2tf32(v[k].x * sc * w.x);
        o.y = f2tf32(v[k].y * sc * w.y);
        o.z = f2tf32(v[k].z * sc * w.z);
        o.w = f2tf32(v[k].w * sc * w.w);
        *reinterpret_cast<float4*>(&g_y[(size_t)t * IF + i]) = o;
    }
}

// ---------------- host launcher ----------------
extern "C" void kernel_launch(void* const* d_in, const int* in_sizes, int n_in,
                              void* d_out, int out_size) {
    const float* hs   = (const float*)d_in[0];
    const float* inw  = (const float*)d_in[1];
    const float* cw   = (const float*)d_in[2];
    const float* cb   = (const float*)d_in[3];
    const float* dtb  = (const float*)d_in[4];
    const float* alog = (const float*)d_in[5];
    const float* Dp   = (const float*)d_in[6];
    const float* nw   = (const float*)d_in[7];
    const float* ow   = (const float*)d_in[8];
    float* out = (float*)d_out;

    void *p_zx = nullptr, *p_y = nullptr, *p_hsr = nullptr, *p_inwT = nullptr, *p_owT = nullptr;
    cudaGetSymbolAddress(&p_zx, g_zx);
    cudaGetSymbolAddress(&p_y, g_y);
    cudaGetSymbolAddress(&p_hsr, g_hsr);
    cudaGetSymbolAddress(&p_inwT, g_inwT);
    cudaGetSymbolAddress(&p_owT, g_owT);

    int smem_gemm = 3 * 2 * STAGE_F * 4;   // 110592
    int smem_cs = (64 * CS_AS + 64 * CS_BS) * 4;
    int smem_y  = (64 * YD_CS * 2 + 64 * YD_XS + 64 * YD_GS + 128) * 4;
    cudaFuncSetAttribute(tf32gemm_ldsm_kernel, cudaFuncAttributeMaxDynamicSharedMemorySize, smem_gemm);
    cudaFuncSetAttribute(chunkstate_mma_kernel, cudaFuncAttributeMaxDynamicSharedMemorySize, smem_cs);
    cudaFuncSetAttribute(ydiag_mma_kernel, cudaFuncAttributeMaxDynamicSharedMemorySize, smem_y);

    // 0. prep: round hs; transpose+round weights
    round_kernel<<<(TTOT * HIDD + 255) / 256, 256>>>(hs, (float*)p_hsr, TTOT * HIDD);
    {
        dim3 g((NPROJ + 31) / 32, (HIDD + 31) / 32);
        transpose_round_kernel<<<g, dim3(32, 8)>>>(inw, (float*)p_inwT, HIDD, NPROJ);
    }
    {
        dim3 g((HIDD + 31) / 32, (IF + 31) / 32);
        transpose_round_kernel<<<g, dim3(32, 8)>>>(ow, (float*)p_owT, IF, HIDD);
    }

    // 1. in_proj GEMM: (8192 x 768) @ (768 x 3352)
    {
        dim3 grid((NPROJ + 127) / 128, TTOT / 128);
        tf32gemm_ldsm_kernel<<<grid, 256, smem_gemm>>>((const float*)p_hsr, (const float*)p_inwT,
                                                       (float*)p_zx, TTOT, NPROJ, HIDD);
    }
    // 2. conv + silu (float4)
    {
        dim3 grid(2, TTOT);
        conv_kernel<<<grid, 224>>>(cw, cb);
    }
    // 3. dt softplus
    dt_kernel<<<(TTOT * HH + 255) / 256, 256>>>(dtb);
    // 4. per-chunk cumsum of A*dt
    acum_kernel<<<BSZ * HH * CN, 256>>>(alog);
    // 5. local chunk states (tf32 mma)
    chunkstate_mma_kernel<<<BSZ * CN * HH, 256, smem_cs>>>();
    // 6. inter-chunk recurrence (wide)
    recur_kernel<<<BSZ * HH * 32, 256>>>();
    // 7. Y_diag + Y_off + D residual (tf32 mma)
    {
        dim3 grid(4, BSZ * CN * HH);
        ydiag_mma_kernel<<<grid, 256, smem_y>>>(Dp);
    }
    // 8. gated RMSNorm (writes tf32-rounded)
    gnorm_kernel<<<TTOT, 128>>>(nw);
    // 9. out_proj GEMM: (8192 x 1536) @ (1536 x 768) -> d_out
    {
        dim3 grid(HIDD / 128, TTOT / 128);
        tf32gemm_ldsm_kernel<<<grid, 256, smem_gemm>>>((const float*)p_y, (const float*)p_owT,
                                                       out, TTOT, HIDD, IF);
    }
}

// round 6
// speedup vs baseline: 2.7402x; 1.0319x over previous
#include <cuda_runtime.h>
#include <cuda_bf16.h>
#include <math.h>
#include <stdint.h>

// ---------------- problem constants ----------------
#define BSZ   2
#define LSEQ  4096
#define TTOT  8192          // BSZ*LSEQ
#define HIDD  768
#define IF    1536          // I
#define NST   128           // N
#define HH    24            // H
#define PP    64            // P
#define CSZ   256           // chunk size
#define CN    16            // LSEQ/CSZ
#define KC    4             // conv kernel
#define NPROJ 3352          // 2*(I+N)+H
#define XBCW  1792          // I+2N

// ---------------- scratch (static device globals; no allocs) ----------------
__device__ float g_zx[TTOT * NPROJ];               // in_proj output (z | xBC | dt)
__device__ float g_xc[TTOT * XBCW];                // conv+silu output
__device__ float g_dt[TTOT * HH];                  // softplus(dt+bias)
__device__ float g_ac[BSZ * HH * CN * CSZ];        // per-chunk inclusive cumsum of A*dt
__device__ float g_ls[BSZ * CN * HH * PP * NST];   // local chunk states
__device__ float g_ps[BSZ * CN * HH * PP * NST];   // prefix states entering chunk
__device__ float g_y [TTOT * IF];                  // y (tf32-rounded after gnorm)
__device__ float g_hsr [TTOT * HIDD];              // hs rounded to tf32
__device__ float g_inwT[NPROJ * HIDD];             // in_proj_w^T, tf32
__device__ float g_owT [HIDD * IF];                // out_proj_w^T, tf32

// ---------------- helpers ----------------
__device__ __forceinline__ float f2tf32(float x) {
    uint32_t r;
    asm("cvt.rna.tf32.f32 %0, %1;" : "=r"(r) : "f"(x));
    return __uint_as_float(r);
}
__device__ __forceinline__ uint32_t fu(float x) { return __float_as_uint(x); }

__device__ __forceinline__ void mma_tf32(float* c, uint32_t a0, uint32_t a1,
                                         uint32_t a2, uint32_t a3,
                                         uint32_t b0, uint32_t b1) {
    asm volatile(
        "mma.sync.aligned.m16n8k8.row.col.f32.tf32.tf32.f32 "
        "{%0,%1,%2,%3}, {%4,%5,%6,%7}, {%8,%9}, {%0,%1,%2,%3};\n"
        : "+f"(c[0]), "+f"(c[1]), "+f"(c[2]), "+f"(c[3])
        : "r"(a0), "r"(a1), "r"(a2), "r"(a3), "r"(b0), "r"(b1));
}
__device__ __forceinline__ void ldsm_x4(uint32_t addr, uint32_t& r0, uint32_t& r1,
                                        uint32_t& r2, uint32_t& r3) {
    asm volatile("ldmatrix.sync.aligned.m8n8.x4.shared.b16 {%0,%1,%2,%3}, [%4];"
                 : "=r"(r0), "=r"(r1), "=r"(r2), "=r"(r3) : "r"(addr));
}
__device__ __forceinline__ void cpasync16(uint32_t daddr, const void* gaddr, bool pred) {
    int sz = pred ? 16 : 0;
    asm volatile("cp.async.cg.shared.global [%0], [%1], 16, %2;"
                 :: "r"(daddr), "l"(gaddr), "r"(sz));
}
#define CP_COMMIT()  asm volatile("cp.async.commit_group;")
#define CP_WAIT3()   asm volatile("cp.async.wait_group 3;")

// ================= TF32 GEMM: ldmatrix + cp.async, BK=16, 5 stages =================
// C = A(MxK) @ Bt^T where Bt is [N][K] row-major, both pre-rounded tf32.
// BM=BN=128, BK=16, 256 thr = 8 warps (warpM 2 x warpN 4), warp tile 64x32.
#define GST 20               // row stride (floats): 16 + 4 pad, conflict-free ldmatrix
#define STAGE_F (128 * GST)  // floats per matrix per stage
#define NSTAGE 5

__global__ __launch_bounds__(256, 2) void tf32gemm_ldsm_kernel(const float* __restrict__ A,
                                                               const float* __restrict__ Bt,
                                                               float* __restrict__ C,
                                                               int M, int N, int K) {
    extern __shared__ float sm[];
    const int tid = threadIdx.x;
    const int lane = tid & 31;
    const int warpId = tid >> 5;
    const int gid = lane >> 2, tig = lane & 3;
    const int warpM = warpId & 1;
    const int warpN = warpId >> 1;
    const int rowBase = blockIdx.y * 128;
    const int colBase = blockIdx.x * 128;
    const int nk = K >> 4;

    uint32_t smBase = (uint32_t)__cvta_generic_to_shared(sm);

    // cp.async per-thread: row = tid>>1, 2 consecutive 16B chunks at (tid&1)*2
    const int cpr = tid >> 1;
    const int cpc = (tid & 1) * 2;
    const int nB = colBase + cpr;
    const bool bOK = nB < N;
    const int nBc = bOK ? nB : 0;
    const uint32_t cpOff = (uint32_t)(cpr * GST + cpc * 4) * 4;

    auto issue = [&](int kt, int stage) {
        int k0 = kt << 4;
        uint32_t sA = smBase + (uint32_t)(stage * 2 * STAGE_F) * 4 + cpOff;
        uint32_t sB = smBase + (uint32_t)((stage * 2 + 1) * STAGE_F) * 4 + cpOff;
        const float* ga = &A[(size_t)(rowBase + cpr) * K + k0 + cpc * 4];
        const float* gb = &Bt[(size_t)nBc * K + k0 + cpc * 4];
        cpasync16(sA, ga, true);
        cpasync16(sA + 16, ga + 4, true);
        cpasync16(sB, gb, bOK);
        cpasync16(sB + 16, gb + 4, bOK);
        CP_COMMIT();
    };

    // ldmatrix per-lane offsets (floats within tile)
    const uint32_t aLaneOff = (uint32_t)((lane & 15) * GST + (lane >> 4) * 4);
    const uint32_t bLaneOff = (uint32_t)(((lane >> 4) * 8 + (lane & 7)) * GST + ((lane >> 3) & 1) * 4);

    float acc[4][4][4];
#pragma unroll
    for (int mt = 0; mt < 4; mt++)
#pragma unroll
        for (int nt = 0; nt < 4; nt++)
#pragma unroll
            for (int e = 0; e < 4; e++) acc[mt][nt][e] = 0.f;

    // prologue: fill 4 stages ahead
#pragma unroll
    for (int p = 0; p < NSTAGE - 1; p++)
        if (p < nk) issue(p, p);

    for (int kt = 0; kt < nk; kt++) {
        CP_WAIT3();            // oldest (kt) group complete in this thread
        __syncthreads();       // visible to all threads; stage (kt-1)%5 now free
        if (kt + NSTAGE - 1 < nk) issue(kt + NSTAGE - 1, (kt + NSTAGE - 1) % NSTAGE);

        int stage = kt % NSTAGE;
        uint32_t aBase = smBase + (uint32_t)(stage * 2 * STAGE_F) * 4;
        uint32_t bBase = smBase + (uint32_t)((stage * 2 + 1) * STAGE_F) * 4;

#pragma unroll
        for (int ks = 0; ks < 2; ks++) {
            uint32_t bfr[4][2];
#pragma unroll
            for (int pair = 0; pair < 2; pair++) {
                uint32_t addr = bBase + ((uint32_t)((warpN * 32 + pair * 16) * GST + ks * 8) + bLaneOff) * 4;
                uint32_t r0, r1, r2, r3;
                ldsm_x4(addr, r0, r1, r2, r3);
                bfr[pair * 2][0] = r0; bfr[pair * 2][1] = r1;
                bfr[pair * 2 + 1][0] = r2; bfr[pair * 2 + 1][1] = r3;
            }
#pragma unroll
            for (int mt = 0; mt < 4; mt++) {
                uint32_t addr = aBase + ((uint32_t)((warpM * 64 + mt * 16) * GST + ks * 8) + aLaneOff) * 4;
                uint32_t a0, a1, a2, a3;
                ldsm_x4(addr, a0, a1, a2, a3);
#pragma unroll
                for (int nt = 0; nt < 4; nt++)
                    mma_tf32(acc[mt][nt], a0, a1, a2, a3, bfr[nt][0], bfr[nt][1]);
            }
        }
    }

    // epilogue
#pragma unroll
    for (int mt = 0; mt < 4; mt++) {
        int r0 = rowBase + warpM * 64 + mt * 16 + gid;
#pragma unroll
        for (int nt = 0; nt < 4; nt++) {
            int c0 = colBase + warpN * 32 + nt * 8 + tig * 2;
            if (c0 < N)     C[(size_t)r0 * N + c0]           = acc[mt][nt][0];
            if (c0 + 1 < N) C[(size_t)r0 * N + c0 + 1]       = acc[mt][nt][1];
            if (c0 < N)     C[(size_t)(r0 + 8) * N + c0]     = acc[mt][nt][2];
            if (c0 + 1 < N) C[(size_t)(r0 + 8) * N + c0 + 1] = acc[mt][nt][3];
        }
    }
}

// ---------------- prep: round / transpose+round ----------------
__global__ __launch_bounds__(256) void round_kernel(const float* __restrict__ src,
                                                    float* __restrict__ dst, int n) {
    int i = blockIdx.x * 256 + threadIdx.x;
    if (i < n) dst[i] = f2tf32(src[i]);
}

__global__ void transpose_round_kernel(const float* __restrict__ src,
                                       float* __restrict__ dst, int R, int Cc) {
    __shared__ float t[32][33];
    int c0 = blockIdx.x * 32, r0 = blockIdx.y * 32;
    int x = c0 + threadIdx.x;
    for (int i = threadIdx.y; i < 32; i += 8) {
        int y = r0 + i;
        if (x < Cc && y < R) t[i][threadIdx.x] = src[(size_t)y * Cc + x];
    }
    __syncthreads();
    int xo = r0 + threadIdx.x;
    for (int i = threadIdx.y; i < 32; i += 8) {
        int yo = c0 + i;
        if (xo < R && yo < Cc) dst[(size_t)yo * R + xo] = f2tf32(t[threadIdx.x][i]);
    }
}

// ---------------- conv1d (causal depthwise, K=4) + bias + silu, float4 ----------------
__global__ __launch_bounds__(224) void conv_kernel(const float* __restrict__ cw,
                                                   const float* __restrict__ cb) {
    int c4 = blockIdx.x * 224 + threadIdx.x;   // 0..447
    int ch = c4 * 4;
    int t  = blockIdx.y;
    int b  = t / LSEQ, l = t % LSEQ;
    float4 acc = *reinterpret_cast<const float4*>(&cb[ch]);
#pragma unroll
    for (int k = 0; k < KC; k++) {
        int lp = l - (KC - 1) + k;
        if (lp >= 0) {
            float4 xv = *reinterpret_cast<const float4*>(&g_zx[(size_t)(b * LSEQ + lp) * NPROJ + IF + ch]);
            float4 wv = *reinterpret_cast<const float4*>(&cw[k * XBCW + ch]);
            acc.x = fmaf(xv.x, wv.x, acc.x);
            acc.y = fmaf(xv.y, wv.y, acc.y);
            acc.z = fmaf(xv.z, wv.z, acc.z);
            acc.w = fmaf(xv.w, wv.w, acc.w);
        }
    }
    acc.x = acc.x / (1.f + expf(-acc.x));
    acc.y = acc.y / (1.f + expf(-acc.y));
    acc.z = acc.z / (1.f + expf(-acc.z));
    acc.w = acc.w / (1.f + expf(-acc.w));
    *reinterpret_cast<float4*>(&g_xc[(size_t)t * XBCW + ch]) = acc;
}

// ---------------- dt: softplus(dt_raw + bias), clip>=0 ----------------
__global__ __launch_bounds__(256) void dt_kernel(const float* __restrict__ dtb) {
    int idx = blockIdx.x * 256 + threadIdx.x;
    if (idx >= TTOT * HH) return;
    int t = idx / HH, h = idx % HH;
    float x = g_zx[(size_t)t * NPROJ + (NPROJ - HH) + h] + dtb[h];
    float sp = (x > 0.f) ? (x + log1pf(expf(-x))) : log1pf(expf(x));
    g_dt[idx] = fmaxf(sp, 0.f);
}

// ---------------- per-chunk inclusive cumsum of A*dt ----------------
__global__ __launch_bounds__(256) void acum_kernel(const float* __restrict__ alog) {
    int bx = blockIdx.x;
    int c  = bx % CN;
    int h  = (bx / CN) % HH;
    int b  = bx / (CN * HH);
    int s  = threadIdx.x;
    int t  = b * LSEQ + c * CSZ + s;
    float A = -expf(alog[h]);
    __shared__ float a[CSZ];
    a[s] = A * g_dt[(size_t)t * HH + h];
    __syncthreads();
    for (int off = 1; off < CSZ; off <<= 1) {
        float add = (s >= off) ? a[s - off] : 0.f;
        __syncthreads();
        a[s] += add;
        __syncthreads();
    }
    g_ac[(size_t)((b * HH + h) * CN + c) * CSZ + s] = a[s];
}

// ================= chunk state via TF32 mma =================
#define CS_AS 68
#define CS_BS 136

__global__ __launch_bounds__(256) void chunkstate_mma_kernel() {
    extern __shared__ float sm[];
    float* As = sm;
    float* Bs = sm + 64 * CS_AS;

    int bx = blockIdx.x;
    int h = bx % HH;
    int c = (bx / HH) % CN;
    int b = bx / (HH * CN);
    int tid = threadIdx.x, lane = tid & 31, warpId = tid >> 5;
    int gid = lane >> 2, tig = lane & 3;
    int warpM = warpId & 1, warpN = warpId >> 1;
    int acbase = ((b * HH + h) * CN + c) * CSZ;
    int tbase = b * LSEQ + c * CSZ;
    float Asum = g_ac[acbase + CSZ - 1];

    float acc[2][4][4];
#pragma unroll
    for (int mt = 0; mt < 2; mt++)
#pragma unroll
        for (int nt = 0; nt < 4; nt++)
#pragma unroll
            for (int e = 0; e < 4; e++) acc[mt][nt][e] = 0.f;

    for (int kt = 0; kt < 4; kt++) {
        for (int i = tid; i < 64 * 64; i += 256) {
            int l = i >> 6, p = i & 63;
            int ts = tbase + kt * 64 + l;
            float v = g_xc[(size_t)ts * XBCW + h * PP + p] * g_dt[(size_t)ts * HH + h];
            As[p * CS_AS + l] = f2tf32(v);
        }
        for (int i = tid; i < 64 * 128; i += 256) {
            int l = i >> 7, n = i & 127;
            int ts = tbase + kt * 64 + l;
            float dec = expf(Asum - g_ac[acbase + kt * 64 + l]);
            Bs[l * CS_BS + n] = f2tf32(g_xc[(size_t)ts * XBCW + IF + n] * dec);
        }
        __syncthreads();
#pragma unroll
        for (int k8 = 0; k8 < 8; k8++) {
            int k0 = k8 * 8;
            uint32_t af[2][4];
#pragma unroll
            for (int mt = 0; mt < 2; mt++) {
                int m = warpM * 32 + mt * 16;
                af[mt][0] = fu(As[(m + gid) * CS_AS + k0 + tig]);
                af[mt][1] = fu(As[(m + gid + 8) * CS_AS + k0 + tig]);
                af[mt][2] = fu(As[(m + gid) * CS_AS + k0 + tig + 4]);
                af[mt][3] = fu(As[(m + gid + 8) * CS_AS + k0 + tig + 4]);
            }
#pragma unroll
            for (int nt = 0; nt < 4; nt++) {
                int n = warpN * 32 + nt * 8 + gid;
                uint32_t b0 = fu(Bs[(k0 + tig) * CS_BS + n]);
                uint32_t b1 = fu(Bs[(k0 + tig + 4) * CS_BS + n]);
#pragma unroll
                for (int mt = 0; mt < 2; mt++)
                    mma_tf32(acc[mt][nt], af[mt][0], af[mt][1], af[mt][2], af[mt][3], b0, b1);
            }
        }
        __syncthreads();
    }

    size_t base = ((size_t)((b * CN + c) * HH + h)) * PP * NST;
#pragma unroll
    for (int mt = 0; mt < 2; mt++) {
        int p0 = warpM * 32 + mt * 16 + gid;
#pragma unroll
        for (int nt = 0; nt < 4; nt++) {
            int n0 = warpN * 32 + nt * 8 + tig * 2;
            g_ls[base + (size_t)p0 * NST + n0]           = acc[mt][nt][0];
            g_ls[base + (size_t)p0 * NST + n0 + 1]       = acc[mt][nt][1];
            g_ls[base + (size_t)(p0 + 8) * NST + n0]     = acc[mt][nt][2];
            g_ls[base + (size_t)(p0 + 8) * NST + n0 + 1] = acc[mt][nt][3];
        }
    }
}

// ---------------- inter-chunk recurrence (1 element/thread) ----------------
__global__ __launch_bounds__(256) void recur_kernel() {
    int blk = blockIdx.x;            // BSZ*HH*32
    int seg = blk & 31;
    int bh  = blk >> 5;
    int b = bh / HH, h = bh % HH;
    int idx = seg * 256 + threadIdx.x;   // 0..8191
    float st = 0.f;
#pragma unroll
    for (int c = 0; c < CN; c++) {
        float es = expf(g_ac[(size_t)((b * HH + h) * CN + c) * CSZ + CSZ - 1]);
        size_t base = ((size_t)((b * CN + c) * HH + h)) * PP * NST;
        g_ps[base + idx] = st;
        st = fmaf(st, es, g_ls[base + idx]);
    }
}

// ================= Y via TF32 mma =================
#define YD_CS 132
#define YD_XS 72
#define YD_GS 68

__global__ __launch_bounds__(256) void ydiag_mma_kernel(const float* __restrict__ Darr) {
    extern __shared__ float sm[];
    float* Cs  = sm;
    float* Bst = Cs + 64 * YD_CS;
    float* Xs  = Bst + 64 * YD_CS;
    float* Gs  = Xs + 64 * YD_XS;
    float* aL  = Gs + 64 * YD_GS;
    float* aS  = aL + 64;

    int lt  = blockIdx.x;
    int bch = blockIdx.y;
    int h = bch % HH;
    int c = (bch / HH) % CN;
    int b = bch / (HH * CN);
    int tid = threadIdx.x, lane = tid & 31, warpId = tid >> 5;
    int gid = lane >> 2, tig = lane & 3;
    int m0 = (warpId & 3) * 16;
    int n0 = (warpId >> 2) * 32;
    int acbase = ((b * HH + h) * CN + c) * CSZ;
    int tbase = b * LSEQ + c * CSZ;

    for (int i = tid; i < 64 * 128; i += 256) {
        int l = i >> 7, n = i & 127;
        Cs[l * YD_CS + n] = f2tf32(g_xc[(size_t)(tbase + lt * 64 + l) * XBCW + IF + NST + n]);
    }
    if (tid < 64) aL[tid] = g_ac[acbase + lt * 64 + tid];

    float accD[4][4];
#pragma unroll
    for (int nt = 0; nt < 4; nt++)
#pragma unroll
        for (int e = 0; e < 4; e++) accD[nt][e] = 0.f;

    for (int st = 0; st <= lt; st++) {
        __syncthreads();
        for (int i = tid; i < 64 * 128; i += 256) {
            int s = i >> 7, n = i & 127;
            Bst[s * YD_CS + n] = f2tf32(g_xc[(size_t)(tbase + st * 64 + s) * XBCW + IF + n]);
        }
        for (int i = tid; i < 64 * 64; i += 256) {
            int s = i >> 6, p = i & 63;
            int ts = tbase + st * 64 + s;
            Xs[s * YD_XS + p] = f2tf32(g_xc[(size_t)ts * XBCW + h * PP + p] * g_dt[(size_t)ts * HH + h]);
        }
        if (tid < 64) aS[tid] = g_ac[acbase + st * 64 + tid];
        __syncthreads();

        float g4[4][4];
#pragma unroll
        for (int nt = 0; nt < 4; nt++)
#pragma unroll
            for (int e = 0; e < 4; e++) g4[nt][e] = 0.f;
#pragma unroll
        for (int k8 = 0; k8 < 16; k8++) {
            int k0 = k8 * 8;
            uint32_t a0 = fu(Cs[(m0 + gid) * YD_CS + k0 + tig]);
            uint32_t a1 = fu(Cs[(m0 + gid + 8) * YD_CS + k0 + tig]);
            uint32_t a2 = fu(Cs[(m0 + gid) * YD_CS + k0 + tig + 4]);
            uint32_t a3 = fu(Cs[(m0 + gid + 8) * YD_CS + k0 + tig + 4]);
#pragma unroll
            for (int nt = 0; nt < 4; nt++) {
                int s = n0 + nt * 8 + gid;
                uint32_t b0 = fu(Bst[s * YD_CS + k0 + tig]);
                uint32_t b1 = fu(Bst[s * YD_CS + k0 + tig + 4]);
                mma_tf32(g4[nt], a0, a1, a2, a3, b0, b1);
            }
        }
        {
            int lA = m0 + gid, lB = lA + 8;
            int glA = lt * 64 + lA, glB = glA + 8;
            float aLA = aL[lA], aLB = aL[lB];
#pragma unroll
            for (int nt = 0; nt < 4; nt++) {
                int s0 = n0 + nt * 8 + tig * 2;
                int gs0 = st * 64 + s0;
                float as0 = aS[s0], as1 = aS[s0 + 1];
                float v0 = (gs0     <= glA) ? g4[nt][0] * expf(aLA - as0) : 0.f;
                float v1 = (gs0 + 1 <= glA) ? g4[nt][1] * expf(aLA - as1) : 0.f;
                float v2 = (gs0     <= glB) ? g4[nt][2] * expf(aLB - as0) : 0.f;
                float v3 = (gs0 + 1 <= glB) ? g4[nt][3] * expf(aLB - as1) : 0.f;
                Gs[lA * YD_GS + s0]     = f2tf32(v0);
                Gs[lA * YD_GS + s0 + 1] = f2tf32(v1);
                Gs[lB * YD_GS + s0]     = f2tf32(v2);
                Gs[lB * YD_GS + s0 + 1] = f2tf32(v3);
            }
        }
        __syncthreads();
#pragma unroll
        for (int k8 = 0; k8 < 8; k8++) {
            int k0 = k8 * 8;
            uint32_t a0 = fu(Gs[(m0 + gid) * YD_GS + k0 + tig]);
            uint32_t a1 = fu(Gs[(m0 + gid + 8) * YD_GS + k0 + tig]);
            uint32_t a2 = fu(Gs[(m0 + gid) * YD_GS + k0 + tig + 4]);
            uint32_t a3 = fu(Gs[(m0 + gid + 8) * YD_GS + k0 + tig + 4]);
#pragma unroll
            for (int nt = 0; nt < 4; nt++) {
                int p = n0 + nt * 8 + gid;
                uint32_t b0 = fu(Xs[(k0 + tig) * YD_XS + p]);
                uint32_t b1 = fu(Xs[(k0 + tig + 4) * YD_XS + p]);
                mma_tf32(accD[nt], a0, a1, a2, a3, b0, b1);
            }
        }
    }

    __syncthreads();
    {
        size_t sbase = ((size_t)((b * CN + c) * HH + h)) * PP * NST;
        for (int i = tid; i < 64 * 128; i += 256) {
            int p = i >> 7, n = i & 127;
            Bst[p * YD_CS + n] = f2tf32(g_ps[sbase + (size_t)p * NST + n]);
        }
    }
    __syncthreads();
    float off4[4][4];
#pragma unroll
    for (int nt = 0; nt < 4; nt++)
#pragma unroll
        for (int e = 0; e < 4; e++) off4[nt][e] = 0.f;
#pragma unroll
    for (int k8 = 0; k8 < 16; k8++) {
        int k0 = k8 * 8;
        uint32_t a0 = fu(Cs[(m0 + gid) * YD_CS + k0 + tig]);
        uint32_t a1 = fu(Cs[(m0 + gid + 8) * YD_CS + k0 + tig]);
        uint32_t a2 = fu(Cs[(m0 + gid) * YD_CS + k0 + tig + 4]);
        uint32_t a3 = fu(Cs[(m0 + gid + 8) * YD_CS + k0 + tig + 4]);
#pragma unroll
        for (int nt = 0; nt < 4; nt++) {
            int p = n0 + nt * 8 + gid;
            uint32_t b0 = fu(Bst[p * YD_CS + k0 + tig]);
            uint32_t b1 = fu(Bst[p * YD_CS + k0 + tig + 4]);
            mma_tf32(off4[nt], a0, a1, a2, a3, b0, b1);
        }
    }

    {
        int lA = m0 + gid, lB = lA + 8;
        float e0 = expf(aL[lA]), e1 = expf(aL[lB]);
        float Dh = Darr[h];
        int tA = tbase + lt * 64 + lA;
        int tB = tbase + lt * 64 + lB;
#pragma unroll
        for (int nt = 0; nt < 4; nt++) {
            int p0 = n0 + nt * 8 + tig * 2;
            float xA0 = g_xc[(size_t)tA * XBCW + h * PP + p0];
            float xA1 = g_xc[(size_t)tA * XBCW + h * PP + p0 + 1];
            float xB0 = g_xc[(size_t)tB * XBCW + h * PP + p0];
            float xB1 = g_xc[(size_t)tB * XBCW + h * PP + p0 + 1];
            g_y[(size_t)tA * IF + h * PP + p0]     = accD[nt][0] + e0 * off4[nt][0] + Dh * xA0;
            g_y[(size_t)tA * IF + h * PP + p0 + 1] = accD[nt][1] + e0 * off4[nt][1] + Dh * xA1;
            g_y[(size_t)tB * IF + h * PP + p0]     = accD[nt][2] + e1 * off4[nt][2] + Dh * xB0;
            g_y[(size_t)tB * IF + h * PP + p0 + 1] = accD[nt][3] + e1 * off4[nt][3] + Dh * xB1;
        }
    }
}

// ---------------- gated RMSNorm (float4, stores tf32-rounded) ----------------
__global__ __launch_bounds__(128) void gnorm_kernel(const float* __restrict__ nw) {
    int t = blockIdx.x;
    int tid = threadIdx.x;
    float4 v[3];
    float ss = 0.f;
#pragma unroll
    for (int k = 0; k < 3; k++) {
        int i = (tid + k * 128) * 4;
        float4 y = *reinterpret_cast<const float4*>(&g_y[(size_t)t * IF + i]);
        float4 z = *reinterpret_cast<const float4*>(&g_zx[(size_t)t * NPROJ + i]);
        float x0 = y.x * (z.x / (1.f + expf(-z.x)));
        float x1 = y.y * (z.y / (1.f + expf(-z.y)));
        float x2 = y.z * (z.z / (1.f + expf(-z.z)));
        float x3 = y.w * (z.w / (1.f + expf(-z.w)));
        v[k] = make_float4(x0, x1, x2, x3);
        ss += x0 * x0 + x1 * x1 + x2 * x2 + x3 * x3;
    }
    __shared__ float red[128];
    __shared__ float s_scale;
    red[tid] = ss;
    __syncthreads();
    for (int o = 64; o > 0; o >>= 1) {
        if (tid < o) red[tid] += red[tid + o];
        __syncthreads();
    }
    if (tid == 0) s_scale = rsqrtf(red[0] / (float)IF + 1e-5f);
    __syncthreads();
    float sc = s_scale;
#pragma unroll
    for (int k = 0; k < 3; k++) {
        int i = (tid + k * 128) * 4;
        float4 w = *reinterpret_cast<const float4*>(&nw[i]);
        float4 o;
        o.x = f2tf32(v[k].x * sc * w.x);
        o.y = f2tf32(v[k].y * sc * w.y);
        o.z = f2tf32(v[k].z * sc * w.z);
        o.w = f2tf32(v[k].w * sc * w.w);
        *reinterpret_cast<float4*>(&g_y[(size_t)t * IF + i]) = o;
    }
}

// ---------------- host launcher ----------------
extern "C" void kernel_launch(void* const* d_in, const int* in_sizes, int n_in,
                              void* d_out, int out_size) {
    const float* hs   = (const float*)d_in[0];
    const float* inw  = (const float*)d_in[1];
    const float* cw   = (const float*)d_in[2];
    const float* cb   = (const float*)d_in[3];
    const float* dtb  = (const float*)d_in[4];
    const float* alog = (const float*)d_in[5];
    const float* Dp   = (const float*)d_in[6];
    const float* nw   = (const float*)d_in[7];
    const float* ow   = (const float*)d_in[8];
    float* out = (float*)d_out;

    void *p_zx = nullptr, *p_y = nullptr, *p_hsr = nullptr, *p_inwT = nullptr, *p_owT = nullptr;
    cudaGetSymbolAddress(&p_zx, g_zx);
    cudaGetSymbolAddress(&p_y, g_y);
    cudaGetSymbolAddress(&p_hsr, g_hsr);
    cudaGetSymbolAddress(&p_inwT, g_inwT);
    cudaGetSymbolAddress(&p_owT, g_owT);

    int smem_gemm = NSTAGE * 2 * STAGE_F * 4;   // 102400
    int smem_cs = (64 * CS_AS + 64 * CS_BS) * 4;
    int smem_y  = (64 * YD_CS * 2 + 64 * YD_XS + 64 * YD_GS + 128) * 4;
    cudaFuncSetAttribute(tf32gemm_ldsm_kernel, cudaFuncAttributeMaxDynamicSharedMemorySize, smem_gemm);
    cudaFuncSetAttribute(chunkstate_mma_kernel, cudaFuncAttributeMaxDynamicSharedMemorySize, smem_cs);
    cudaFuncSetAttribute(ydiag_mma_kernel, cudaFuncAttributeMaxDynamicSharedMemorySize, smem_y);

    // 0. prep: round hs; transpose+round weights
    round_kernel<<<(TTOT * HIDD + 255) / 256, 256>>>(hs, (float*)p_hsr, TTOT * HIDD);
    {
        dim3 g((NPROJ + 31) / 32, (HIDD + 31) / 32);
        transpose_round_kernel<<<g, dim3(32, 8)>>>(inw, (float*)p_inwT, HIDD, NPROJ);
    }
    {
        dim3 g((HIDD + 31) / 32, (IF + 31) / 32);
        transpose_round_kernel<<<g, dim3(32, 8)>>>(ow, (float*)p_owT, IF, HIDD);
    }

    // 1. in_proj GEMM: (8192 x 768) @ (768 x 3352)
    {
        dim3 grid((NPROJ + 127) / 128, TTOT / 128);
        tf32gemm_ldsm_kernel<<<grid, 256, smem_gemm>>>((const float*)p_hsr, (const float*)p_inwT,
                                                       (float*)p_zx, TTOT, NPROJ, HIDD);
    }
    // 2. conv + silu (float4)
    {
        dim3 grid(2, TTOT);
        conv_kernel<<<grid, 224>>>(cw, cb);
    }
    // 3. dt softplus
    dt_kernel<<<(TTOT * HH + 255) / 256, 256>>>(dtb);
    // 4. per-chunk cumsum of A*dt
    acum_kernel<<<BSZ * HH * CN, 256>>>(alog);
    // 5. local chunk states (tf32 mma)
    chunkstate_mma_kernel<<<BSZ * CN * HH, 256, smem_cs>>>();
    // 6. inter-chunk recurrence (wide)
    recur_kernel<<<BSZ * HH * 32, 256>>>();
    // 7. Y_diag + Y_off + D residual (tf32 mma)
    {
        dim3 grid(4, BSZ * CN * HH);
        ydiag_mma_kernel<<<grid, 256, smem_y>>>(Dp);
    }
    // 8. gated RMSNorm (writes tf32-rounded)
    gnorm_kernel<<<TTOT, 128>>>(nw);
    // 9. out_proj GEMM: (8192 x 1536) @ (1536 x 768) -> d_out
    {
        dim3 grid(HIDD / 128, TTOT / 128);
        tf32gemm_ldsm_kernel<<<grid, 256, smem_gemm>>>((const float*)p_y, (const float*)p_owT,
                                                       out, TTOT, HIDD, IF);
    }
}